// round 12
// baseline (speedup 1.0000x reference)
#include <cuda_runtime.h>
#include <math.h>
#include <stdint.h>

#define NB 4
#define SEQ 2048
#define DMODEL 1024
#define NH 16
#define HD 64
#define NTOK (NB*SEQ)      /* 8192 */
#define DFF 4096

// ---------------- scratch (device globals; no allocations allowed) ----------
__device__ float g_ln [(size_t)NTOK*DMODEL];
__device__ float g_q  [(size_t)NTOK*DMODEL];
__device__ float g_k  [(size_t)NTOK*DMODEL];
__device__ float g_v  [(size_t)NTOK*DMODEL];
__device__ float g_ctx[(size_t)NTOK*DMODEL];
__device__ float g_x1 [(size_t)NTOK*DMODEL];
__device__ float g_h2 [(size_t)NTOK*DFF];
// tf32-pre-rounded weight copies (same layout as the originals)
__device__ float g_wqkvR[(size_t)DMODEL*3*DMODEL];
__device__ float g_woutR[(size_t)DMODEL*DMODEL];
__device__ float g_w1R  [(size_t)DMODEL*DFF];
__device__ float g_w2R  [(size_t)DFF*DMODEL];

// ---------------- helpers ----------------------------------------------------
__device__ __forceinline__ float tf32r(float x){
    unsigned u; asm("cvt.rna.tf32.f32 %0, %1;" : "=r"(u) : "f"(x));
    return __uint_as_float(u);
}
__device__ __forceinline__ float gelu_fast(float x){
    float u = 0.7978845608028654f*(x + 0.044715f*x*x*x);
    float th; asm("tanh.approx.f32 %0, %1;" : "=f"(th) : "f"(u));
    return 0.5f*x*(1.0f + th);
}
__device__ __forceinline__ void mma8(float* c, const unsigned* a, const unsigned* b){
    asm volatile(
        "mma.sync.aligned.m16n8k8.row.col.f32.tf32.tf32.f32 "
        "{%0,%1,%2,%3}, {%4,%5,%6,%7}, {%8,%9}, {%0,%1,%2,%3};\n"
        : "+f"(c[0]), "+f"(c[1]), "+f"(c[2]), "+f"(c[3])
        : "r"(a[0]), "r"(a[1]), "r"(a[2]), "r"(a[3]), "r"(b[0]), "r"(b[1]));
}
__device__ __forceinline__ void cpa16(void* smem_dst, const void* gsrc){
    unsigned d = (unsigned)__cvta_generic_to_shared(smem_dst);
    asm volatile("cp.async.cg.shared.global [%0], [%1], 16;\n" :: "r"(d), "l"(gsrc));
}
#define CP_COMMIT() asm volatile("cp.async.commit_group;\n" ::: "memory")
#define CP_WAIT1()  asm volatile("cp.async.wait_group 1;\n" ::: "memory")

// ---------------- weight tf32 pre-round --------------------------------------
__global__ __launch_bounds__(256) void round_tf32_kernel(
    const float* __restrict__ src, float* __restrict__ dst)
{
    size_t i = ((size_t)blockIdx.x*256 + threadIdx.x)*4;
    float4 v = *(const float4*)(src + i);
    v.x = tf32r(v.x); v.y = tf32r(v.y); v.z = tf32r(v.z); v.w = tf32r(v.w);
    *(float4*)(dst + i) = v;
}

// ---------------- LayerNorm (tf32-rounded output) ----------------------------
__global__ __launch_bounds__(256) void ln_kernel(const float* __restrict__ x,
        const float* __restrict__ g, const float* __restrict__ s,
        float* __restrict__ out)
{
    int row = blockIdx.x;
    int t = threadIdx.x;
    const float4* xr = (const float4*)(x + (size_t)row*DMODEL);
    float4 v = xr[t];
    float sum = v.x+v.y+v.z+v.w;
    float sq  = v.x*v.x+v.y*v.y+v.z*v.z+v.w*v.w;
    #pragma unroll
    for (int o=16;o>0;o>>=1){
        sum += __shfl_xor_sync(0xffffffffu, sum, o);
        sq  += __shfl_xor_sync(0xffffffffu, sq , o);
    }
    __shared__ float red[16];
    if ((t&31)==0){ red[t>>5] = sum; red[8+(t>>5)] = sq; }
    __syncthreads();
    sum = 0.0f; sq = 0.0f;
    #pragma unroll
    for (int w=0; w<8; w++){ sum += red[w]; sq += red[8+w]; }
    float mean = sum * (1.0f/DMODEL);
    float var  = sq  * (1.0f/DMODEL) - mean*mean;
    float rinv = rsqrtf(var + 1e-5f);
    float4 gv = ((const float4*)g)[t];
    float4 sv = ((const float4*)s)[t];
    float4 o;
    o.x = tf32r((v.x-mean)*rinv*gv.x + sv.x);
    o.y = tf32r((v.y-mean)*rinv*gv.y + sv.y);
    o.z = tf32r((v.z-mean)*rinv*gv.z + sv.z);
    o.w = tf32r((v.w-mean)*rinv*gv.w + sv.w);
    ((float4*)(out + (size_t)row*DMODEL))[t] = o;
}

// ---------------- TF32 tensor-core GEMM (3-stage cp.async pipeline) ----------
// 128x128 CTA tile, K-slab 32, 8 warps (2x4), warp tile 64x32 as 4x4 m16n8k8.
// Explicit double-buffered fragment registers: load k-step ks+1 while issuing
// ks's 16 MMAs (no occupancy cap -> no spills; ptxas gets the ILP directly).
// EPI: 0 plain, 1 +bias+residual, 2 +bias+gelu(->tf32), 3 qkv scatter.
struct GSmem {
    float As[3][128][36];
    float Bs[3][32][136];
};
extern __shared__ char gsm_raw[];

template<int EPI>
__global__ __launch_bounds__(256) void tfgemm_kernel(
    const float* __restrict__ A, const float* __restrict__ B,
    const float* __restrict__ bias, const float* __restrict__ res,
    float* __restrict__ C,
    float* __restrict__ Oq, float* __restrict__ Ok, float* __restrict__ Ov,
    int M, int N, int K)
{
    GSmem* sm = (GSmem*)gsm_raw;
    int t = threadIdx.x;
    int lane = t & 31, w = t >> 5;
    int wm = w >> 2, wn = w & 3;        // warp grid 2 x 4
    int g = lane >> 2, tig = lane & 3;  // mma groupID / thread-in-group
    int m0 = blockIdx.y * 128, n0 = blockIdx.x * 128;

    const int arow = t >> 1, acol = (t & 1) * 4;   // A: 128 rows x 32 cols
    const int brow = t >> 3, bcol = (t & 7) * 4;   // B: 32 rows x 128 cols
    const float* Abase = A + (size_t)(m0 + arow)*K + acol;
    const float* Bbase = B + (size_t)brow*N + n0 + bcol;

    float acc[4][4][4];
    #pragma unroll
    for (int i=0;i<4;i++)
    #pragma unroll
    for (int j=0;j<4;j++)
    #pragma unroll
    for (int r=0;r<4;r++) acc[i][j][r] = 0.0f;

    // issue one K-slab's async copies into stage slab%3
    auto issue = [&](int slab){
        int buf = slab % 3;
        const float* Ap = Abase + slab*32;
        #pragma unroll
        for (int i=0;i<4;i++)
            cpa16(&sm->As[buf][arow][acol + 8*i], Ap + 8*i);
        const float* Bp = Bbase + (size_t)slab*32*N;
        #pragma unroll
        for (int i=0;i<4;i++)
            cpa16(&sm->Bs[buf][brow][bcol + 32*i], Bp + 32*i);
    };

    // load one k-step's fragments from stage `buf`
    auto loadfr = [&](int buf, int ks, unsigned af[4][4], unsigned bf[4][2]){
        int kk = ks*8;
        #pragma unroll
        for (int mt=0; mt<4; mt++){
            int m = wm*64 + mt*16;
            af[mt][0] = __float_as_uint(sm->As[buf][m+g  ][kk+tig  ]);
            af[mt][1] = __float_as_uint(sm->As[buf][m+g+8][kk+tig  ]);
            af[mt][2] = __float_as_uint(sm->As[buf][m+g  ][kk+tig+4]);
            af[mt][3] = __float_as_uint(sm->As[buf][m+g+8][kk+tig+4]);
        }
        #pragma unroll
        for (int nt=0; nt<4; nt++){
            int n = wn*32 + nt*8;
            bf[nt][0] = __float_as_uint(sm->Bs[buf][kk+tig  ][n+g]);
            bf[nt][1] = __float_as_uint(sm->Bs[buf][kk+tig+4][n+g]);
        }
    };

    issue(0); CP_COMMIT();
    issue(1); CP_COMMIT();

    unsigned af[2][4][4], bf[2][4][2];

    int nslab = K >> 5;
    for (int s=0; s<nslab; s++){
        int buf = s % 3;
        CP_WAIT1();                 // slab s landed (one newer may be in flight)
        __syncthreads();            // visibility + all warps done with buf (s-1)%3
        if (s + 2 < nslab) issue(s + 2);
        CP_COMMIT();                // exactly one group per iteration (may be empty)

        loadfr(buf, 0, af[0], bf[0]);
        #pragma unroll
        for (int ks=0; ks<4; ks++){
            int cur = ks & 1, nxt = cur ^ 1;
            if (ks < 3) loadfr(buf, ks+1, af[nxt], bf[nxt]);
            #pragma unroll
            for (int mt=0; mt<4; mt++)
            #pragma unroll
            for (int nt=0; nt<4; nt++)
                mma8(acc[mt][nt], af[cur][mt], bf[cur][nt]);
        }
    }

    // ---------------- epilogue (float2 per half-fragment) --------------
    #pragma unroll
    for (int mt=0; mt<4; mt++){
        #pragma unroll
        for (int nt=0; nt<4; nt++){
            int col = n0 + wn*32 + nt*8 + 2*tig;
            #pragma unroll
            for (int hh=0; hh<2; hh++){
                int row = m0 + wm*64 + mt*16 + g + hh*8;
                float2 v = make_float2(acc[mt][nt][hh*2+0], acc[mt][nt][hh*2+1]);
                if (EPI == 0){
                    *(float2*)(C + (size_t)row*N + col) = v;
                } else if (EPI == 1){
                    float2 bb = *(const float2*)(bias + col);
                    float2 rr = *(const float2*)(res + (size_t)row*N + col);
                    v.x += bb.x + rr.x; v.y += bb.y + rr.y;
                    *(float2*)(C + (size_t)row*N + col) = v;
                } else if (EPI == 2){
                    float2 bb = *(const float2*)(bias + col);
                    v.x = tf32r(gelu_fast(v.x + bb.x));
                    v.y = tf32r(gelu_fast(v.y + bb.y));
                    *(float2*)(C + (size_t)row*N + col) = v;
                } else {
                    int which = col >> 10;
                    int h = (col >> 6) & (NH-1);
                    int d = col & (HD-1);
                    int b = row >> 11;
                    int sg = row & (SEQ-1);
                    float* o = (which==0) ? Oq : ((which==1) ? Ok : Ov);
                    *(float2*)(o + ((size_t)((b*NH + h)*SEQ + sg))*HD + d) = v;
                }
            }
        }
    }
}

// ---------------- Flash attention (TF32 mma, causal) ------------------------
// 64-query tile, 64-key steps, 128 threads / 4 warps; warp w owns query rows
// [w*16, w*16+16): softmax row stats warp-local, P warp-private.
struct FlashSmemT {
    float Qs[64][68];
    float Ks[64][68];
    float Vs[64][72];
    float Ps[64][68];
};
extern __shared__ char flash_dyn[];

__global__ __launch_bounds__(128) void flash_tc_kernel(
    const float* __restrict__ Q, const float* __restrict__ K,
    const float* __restrict__ V, float* __restrict__ ctx)
{
    FlashSmemT* sm = (FlashSmemT*)flash_dyn;
    int t = threadIdx.x;
    int lane = t & 31, w = t >> 5;
    int g = lane >> 2, tig = lane & 3;
    int qb = blockIdx.x, bh = blockIdx.y;
    int mw = w * 16;

    const float* Qb = Q + ((size_t)bh*SEQ + (size_t)qb*64)*HD;
    const float* Kb = K + (size_t)bh*SEQ*HD;
    const float* Vb = V + (size_t)bh*SEQ*HD;

    #pragma unroll
    for (int i=0;i<8;i++){
        int cidx = t + 128*i;
        int r = cidx >> 4, c = (cidx & 15) * 4;
        float4 v = *(const float4*)(Qb + r*HD + c);
        sm->Qs[r][c+0] = tf32r(v.x*0.125f);
        sm->Qs[r][c+1] = tf32r(v.y*0.125f);
        sm->Qs[r][c+2] = tf32r(v.z*0.125f);
        sm->Qs[r][c+3] = tf32r(v.w*0.125f);
    }

    float m0 = -1e30f, m1 = -1e30f, l0 = 0.0f, l1 = 0.0f;
    float acc_o[8][4];
    #pragma unroll
    for (int nt=0; nt<8; nt++)
    #pragma unroll
    for (int r=0; r<4; r++) acc_o[nt][r] = 0.0f;

    for (int jt=0; jt<=qb; jt++){
        __syncthreads();
        const float* Kp = Kb + (size_t)jt*64*HD;
        const float* Vp = Vb + (size_t)jt*64*HD;
        #pragma unroll
        for (int i=0;i<8;i++){
            int cidx = t + 128*i;
            int r = cidx >> 4, c = (cidx & 15) * 4;
            float4 kv = *(const float4*)(Kp + r*HD + c);
            sm->Ks[r][c+0] = tf32r(kv.x); sm->Ks[r][c+1] = tf32r(kv.y);
            sm->Ks[r][c+2] = tf32r(kv.z); sm->Ks[r][c+3] = tf32r(kv.w);
            float4 vv = *(const float4*)(Vp + r*HD + c);
            sm->Vs[r][c+0] = tf32r(vv.x); sm->Vs[r][c+1] = tf32r(vv.y);
            sm->Vs[r][c+2] = tf32r(vv.z); sm->Vs[r][c+3] = tf32r(vv.w);
        }
        __syncthreads();

        float acc_s[8][4];
        #pragma unroll
        for (int nt=0; nt<8; nt++)
        #pragma unroll
        for (int r=0; r<4; r++) acc_s[nt][r] = 0.0f;
        #pragma unroll
        for (int ks=0; ks<8; ks++){
            int kk = ks*8;
            unsigned af[4];
            af[0] = __float_as_uint(sm->Qs[mw+g  ][kk+tig  ]);
            af[1] = __float_as_uint(sm->Qs[mw+g+8][kk+tig  ]);
            af[2] = __float_as_uint(sm->Qs[mw+g  ][kk+tig+4]);
            af[3] = __float_as_uint(sm->Qs[mw+g+8][kk+tig+4]);
            #pragma unroll
            for (int nt=0; nt<8; nt++){
                unsigned bf[2];
                bf[0] = __float_as_uint(sm->Ks[nt*8+g][kk+tig  ]);
                bf[1] = __float_as_uint(sm->Ks[nt*8+g][kk+tig+4]);
                mma8(acc_s[nt], af, bf);
            }
        }

        if (jt == qb){
            int i0 = mw + g;
            #pragma unroll
            for (int nt=0; nt<8; nt++){
                int j = nt*8 + 2*tig;
                if (j   > i0)   acc_s[nt][0] = -1e30f;
                if (j+1 > i0)   acc_s[nt][1] = -1e30f;
                if (j   > i0+8) acc_s[nt][2] = -1e30f;
                if (j+1 > i0+8) acc_s[nt][3] = -1e30f;
            }
        }

        float mx0 = -1e30f, mx1 = -1e30f;
        #pragma unroll
        for (int nt=0; nt<8; nt++){
            mx0 = fmaxf(mx0, fmaxf(acc_s[nt][0], acc_s[nt][1]));
            mx1 = fmaxf(mx1, fmaxf(acc_s[nt][2], acc_s[nt][3]));
        }
        mx0 = fmaxf(mx0, __shfl_xor_sync(0xffffffffu, mx0, 1));
        mx0 = fmaxf(mx0, __shfl_xor_sync(0xffffffffu, mx0, 2));
        mx1 = fmaxf(mx1, __shfl_xor_sync(0xffffffffu, mx1, 1));
        mx1 = fmaxf(mx1, __shfl_xor_sync(0xffffffffu, mx1, 2));
        float mn0 = fmaxf(m0, mx0), mn1 = fmaxf(m1, mx1);
        float al0 = __expf(m0 - mn0), al1 = __expf(m1 - mn1);
        float s0 = 0.0f, s1 = 0.0f;
        #pragma unroll
        for (int nt=0; nt<8; nt++){
            float p00 = __expf(acc_s[nt][0] - mn0);
            float p01 = __expf(acc_s[nt][1] - mn0);
            float p10 = __expf(acc_s[nt][2] - mn1);
            float p11 = __expf(acc_s[nt][3] - mn1);
            s0 += p00 + p01; s1 += p10 + p11;
            *(float2*)&sm->Ps[mw+g  ][nt*8 + 2*tig] = make_float2(tf32r(p00), tf32r(p01));
            *(float2*)&sm->Ps[mw+g+8][nt*8 + 2*tig] = make_float2(tf32r(p10), tf32r(p11));
        }
        s0 += __shfl_xor_sync(0xffffffffu, s0, 1);
        s0 += __shfl_xor_sync(0xffffffffu, s0, 2);
        s1 += __shfl_xor_sync(0xffffffffu, s1, 1);
        s1 += __shfl_xor_sync(0xffffffffu, s1, 2);
        m0 = mn0; m1 = mn1;
        l0 = l0*al0 + s0; l1 = l1*al1 + s1;
        #pragma unroll
        for (int nt=0; nt<8; nt++){
            acc_o[nt][0] *= al0; acc_o[nt][1] *= al0;
            acc_o[nt][2] *= al1; acc_o[nt][3] *= al1;
        }

        __syncwarp();

        #pragma unroll
        for (int ks=0; ks<8; ks++){
            int kk = ks*8;
            unsigned af[4];
            af[0] = __float_as_uint(sm->Ps[mw+g  ][kk+tig  ]);
            af[1] = __float_as_uint(sm->Ps[mw+g+8][kk+tig  ]);
            af[2] = __float_as_uint(sm->Ps[mw+g  ][kk+tig+4]);
            af[3] = __float_as_uint(sm->Ps[mw+g+8][kk+tig+4]);
            #pragma unroll
            for (int nt=0; nt<8; nt++){
                unsigned bf[2];
                bf[0] = __float_as_uint(sm->Vs[kk+tig  ][nt*8+g]);
                bf[1] = __float_as_uint(sm->Vs[kk+tig+4][nt*8+g]);
                mma8(acc_o[nt], af, bf);
            }
        }
    }

    // normalize, tf32-round (feeds Wout GEMM), write ctx in [B,S,D]
    float inv0 = 1.0f/l0, inv1 = 1.0f/l1;
    int b = bh >> 4, h = bh & (NH-1);
    int r0 = qb*64 + mw + g, r1 = r0 + 8;
    #pragma unroll
    for (int nt=0; nt<8; nt++){
        int col = h*HD + nt*8 + 2*tig;
        *(float2*)(ctx + (size_t)(b*SEQ + r0)*DMODEL + col) =
            make_float2(tf32r(acc_o[nt][0]*inv0), tf32r(acc_o[nt][1]*inv0));
        *(float2*)(ctx + (size_t)(b*SEQ + r1)*DMODEL + col) =
            make_float2(tf32r(acc_o[nt][2]*inv1), tf32r(acc_o[nt][3]*inv1));
    }
}

// ---------------- launch ----------------------------------------------------
extern "C" void kernel_launch(void* const* d_in, const int* in_sizes, int n_in,
                              void* d_out, int out_size)
{
    (void)in_sizes; (void)n_in; (void)out_size;
    const float* x    = (const float*)d_in[0];
    const float* Wqkv = (const float*)d_in[1];
    const float* Wout = (const float*)d_in[2];
    const float* bout = (const float*)d_in[3];
    const float* W1   = (const float*)d_in[4];
    const float* b1   = (const float*)d_in[5];
    const float* W2   = (const float*)d_in[6];
    const float* b2   = (const float*)d_in[7];
    const float* g1   = (const float*)d_in[8];
    const float* s1   = (const float*)d_in[9];
    const float* g2   = (const float*)d_in[10];
    const float* s2   = (const float*)d_in[11];
    float* out = (float*)d_out;

    float *p_ln, *p_q, *p_k, *p_v, *p_ctx, *p_x1, *p_h2;
    float *p_wqkvR, *p_woutR, *p_w1R, *p_w2R;
    cudaGetSymbolAddress((void**)&p_ln,  g_ln);
    cudaGetSymbolAddress((void**)&p_q,   g_q);
    cudaGetSymbolAddress((void**)&p_k,   g_k);
    cudaGetSymbolAddress((void**)&p_v,   g_v);
    cudaGetSymbolAddress((void**)&p_ctx, g_ctx);
    cudaGetSymbolAddress((void**)&p_x1,  g_x1);
    cudaGetSymbolAddress((void**)&p_h2,  g_h2);
    cudaGetSymbolAddress((void**)&p_wqkvR, g_wqkvR);
    cudaGetSymbolAddress((void**)&p_woutR, g_woutR);
    cudaGetSymbolAddress((void**)&p_w1R,   g_w1R);
    cudaGetSymbolAddress((void**)&p_w2R,   g_w2R);

    const int gsmem = (int)sizeof(GSmem);
    const int fsmem = (int)sizeof(FlashSmemT);
    cudaFuncSetAttribute(tfgemm_kernel<1>, cudaFuncAttributeMaxDynamicSharedMemorySize, gsmem);
    cudaFuncSetAttribute(tfgemm_kernel<2>, cudaFuncAttributeMaxDynamicSharedMemorySize, gsmem);
    cudaFuncSetAttribute(tfgemm_kernel<3>, cudaFuncAttributeMaxDynamicSharedMemorySize, gsmem);
    cudaFuncSetAttribute(flash_tc_kernel, cudaFuncAttributeMaxDynamicSharedMemorySize, fsmem);

    // 0) tf32 pre-round of all weights (once per launch; ~30us total)
    round_tf32_kernel<<<(DMODEL*3*DMODEL)/1024, 256>>>(Wqkv, p_wqkvR);
    round_tf32_kernel<<<(DMODEL*DMODEL)/1024,   256>>>(Wout, p_woutR);
    round_tf32_kernel<<<(DMODEL*DFF)/1024,      256>>>(W1,   p_w1R);
    round_tf32_kernel<<<(DFF*DMODEL)/1024,      256>>>(W2,   p_w2R);

    // 1) ln1 (rounds its output)
    ln_kernel<<<NTOK, 256>>>(x, g1, s1, p_ln);
    // 2) qkv gemm + scatter to [B,H,S,HD]
    tfgemm_kernel<3><<<dim3(3*DMODEL/128, NTOK/128), 256, gsmem>>>(
        p_ln, p_wqkvR, nullptr, nullptr, nullptr, p_q, p_k, p_v,
        NTOK, 3*DMODEL, DMODEL);
    // 3) causal flash attention (tensor cores; rounds ctx output)
    flash_tc_kernel<<<dim3(SEQ/64, NB*NH), 128, fsmem>>>(p_q, p_k, p_v, p_ctx);
    // 4) out proj + bias + residual(x)
    tfgemm_kernel<1><<<dim3(DMODEL/128, NTOK/128), 256, gsmem>>>(
        p_ctx, p_woutR, bout, x, p_x1, nullptr, nullptr, nullptr,
        NTOK, DMODEL, DMODEL);
    // 5) ln2 (rounds its output)
    ln_kernel<<<NTOK, 256>>>(p_x1, g2, s2, p_ln);
    // 6) W1 + bias + gelu (rounds its output)
    tfgemm_kernel<2><<<dim3(DFF/128, NTOK/128), 256, gsmem>>>(
        p_ln, p_w1R, b1, nullptr, p_h2, nullptr, nullptr, nullptr,
        NTOK, DFF, DMODEL);
    // 7) W2 + bias + residual(x1) -> out
    tfgemm_kernel<1><<<dim3(DMODEL/128, NTOK/128), 256, gsmem>>>(
        p_h2, p_w2R, b2, p_x1, out, nullptr, nullptr, nullptr,
        NTOK, DMODEL, DFF);
}

// round 13
// speedup vs baseline: 1.2065x; 1.2065x over previous
#include <cuda_runtime.h>
#include <math.h>
#include <stdint.h>

#define NB 4
#define SEQ 2048
#define DMODEL 1024
#define NH 16
#define HD 64
#define NTOK (NB*SEQ)      /* 8192 */
#define DFF 4096

// ---------------- scratch (device globals; no allocations allowed) ----------
__device__ float g_ln [(size_t)NTOK*DMODEL];
__device__ float g_q  [(size_t)NTOK*DMODEL];
__device__ float g_k  [(size_t)NTOK*DMODEL];
__device__ float g_v  [(size_t)NTOK*DMODEL];
__device__ float g_ctx[(size_t)NTOK*DMODEL];
__device__ float g_x1 [(size_t)NTOK*DMODEL];
__device__ float g_h2 [(size_t)NTOK*DFF];
// tf32-pre-rounded weight copies (same layout as the originals)
__device__ float g_wqkvR[(size_t)DMODEL*3*DMODEL];
__device__ float g_woutR[(size_t)DMODEL*DMODEL];
__device__ float g_w1R  [(size_t)DMODEL*DFF];
__device__ float g_w2R  [(size_t)DFF*DMODEL];

// ---------------- helpers ----------------------------------------------------
__device__ __forceinline__ float tf32r(float x){
    unsigned u; asm("cvt.rna.tf32.f32 %0, %1;" : "=r"(u) : "f"(x));
    return __uint_as_float(u);
}
__device__ __forceinline__ float gelu_fast(float x){
    float u = 0.7978845608028654f*(x + 0.044715f*x*x*x);
    float th; asm("tanh.approx.f32 %0, %1;" : "=f"(th) : "f"(u));
    return 0.5f*x*(1.0f + th);
}
__device__ __forceinline__ void mma8(float* c, const unsigned* a, const unsigned* b){
    asm volatile(
        "mma.sync.aligned.m16n8k8.row.col.f32.tf32.tf32.f32 "
        "{%0,%1,%2,%3}, {%4,%5,%6,%7}, {%8,%9}, {%0,%1,%2,%3};\n"
        : "+f"(c[0]), "+f"(c[1]), "+f"(c[2]), "+f"(c[3])
        : "r"(a[0]), "r"(a[1]), "r"(a[2]), "r"(a[3]), "r"(b[0]), "r"(b[1]));
}
__device__ __forceinline__ void cpa16(void* smem_dst, const void* gsrc){
    unsigned d = (unsigned)__cvta_generic_to_shared(smem_dst);
    asm volatile("cp.async.cg.shared.global [%0], [%1], 16;\n" :: "r"(d), "l"(gsrc));
}
#define CP_COMMIT() asm volatile("cp.async.commit_group;\n" ::: "memory")
#define CP_WAIT0()  asm volatile("cp.async.wait_group 0;\n" ::: "memory")

// ---------------- weight tf32 pre-round --------------------------------------
__global__ __launch_bounds__(256) void round_tf32_kernel(
    const float* __restrict__ src, float* __restrict__ dst)
{
    size_t i = ((size_t)blockIdx.x*256 + threadIdx.x)*4;
    float4 v = *(const float4*)(src + i);
    v.x = tf32r(v.x); v.y = tf32r(v.y); v.z = tf32r(v.z); v.w = tf32r(v.w);
    *(float4*)(dst + i) = v;
}

// ---------------- LayerNorm (tf32-rounded output) ----------------------------
__global__ __launch_bounds__(256) void ln_kernel(const float* __restrict__ x,
        const float* __restrict__ g, const float* __restrict__ s,
        float* __restrict__ out)
{
    int row = blockIdx.x;
    int t = threadIdx.x;
    const float4* xr = (const float4*)(x + (size_t)row*DMODEL);
    float4 v = xr[t];
    float sum = v.x+v.y+v.z+v.w;
    float sq  = v.x*v.x+v.y*v.y+v.z*v.z+v.w*v.w;
    #pragma unroll
    for (int o=16;o>0;o>>=1){
        sum += __shfl_xor_sync(0xffffffffu, sum, o);
        sq  += __shfl_xor_sync(0xffffffffu, sq , o);
    }
    __shared__ float red[16];
    if ((t&31)==0){ red[t>>5] = sum; red[8+(t>>5)] = sq; }
    __syncthreads();
    sum = 0.0f; sq = 0.0f;
    #pragma unroll
    for (int w=0; w<8; w++){ sum += red[w]; sq += red[8+w]; }
    float mean = sum * (1.0f/DMODEL);
    float var  = sq  * (1.0f/DMODEL) - mean*mean;
    float rinv = rsqrtf(var + 1e-5f);
    float4 gv = ((const float4*)g)[t];
    float4 sv = ((const float4*)s)[t];
    float4 o;
    o.x = tf32r((v.x-mean)*rinv*gv.x + sv.x);
    o.y = tf32r((v.y-mean)*rinv*gv.y + sv.y);
    o.z = tf32r((v.z-mean)*rinv*gv.z + sv.z);
    o.w = tf32r((v.w-mean)*rinv*gv.w + sv.w);
    ((float4*)(out + (size_t)row*DMODEL))[t] = o;
}

// ---------------- TF32 tensor-core GEMM --------------------------------------
// 128x64 CTA tile, 128 threads / 4 warps (2x2 warp grid, 64x32 warp tile),
// K-slab 32, R5-style 2-stage cp.async double buffer, 4 CTAs/SM.
// Pads: As[...][36] -> A-frag banks 4g+tig (conflict-free);
//       Bs[...][72] -> B-frag banks 8tig+g (72 % 32 == 8, conflict-free).
// EPI: 0 plain, 1 +bias+residual, 2 +bias+gelu(->tf32), 3 qkv scatter.
struct GSmem {
    float As[2][128][36];
    float Bs[2][32][72];
};
extern __shared__ char gsm_raw[];

template<int EPI>
__global__ __launch_bounds__(128,4) void tfgemm_kernel(
    const float* __restrict__ A, const float* __restrict__ B,
    const float* __restrict__ bias, const float* __restrict__ res,
    float* __restrict__ C,
    float* __restrict__ Oq, float* __restrict__ Ok, float* __restrict__ Ov,
    int M, int N, int K)
{
    GSmem* sm = (GSmem*)gsm_raw;
    int t = threadIdx.x;
    int lane = t & 31, w = t >> 5;
    int wm = w >> 1, wn = w & 1;        // warp grid 2 x 2
    int g = lane >> 2, tig = lane & 3;  // mma groupID / thread-in-group
    int m0 = blockIdx.y * 128, n0 = blockIdx.x * 64;

    // A: 128 rows x 32 cols -> thread t owns row t, 8 chunks of 16B
    // B: 32 rows x 64 cols  -> thread t owns row t>>2, 4 chunks of 16B
    const float* Abase = A + (size_t)(m0 + t)*K;
    const int brow = t >> 2, bcol4 = (t & 3)*4;
    const float* Bbase = B + (size_t)brow*N + n0 + bcol4;

    float acc[4][4][4];
    #pragma unroll
    for (int i=0;i<4;i++)
    #pragma unroll
    for (int j=0;j<4;j++)
    #pragma unroll
    for (int r=0;r<4;r++) acc[i][j][r] = 0.0f;

    // issue one K-slab's async copies into stage `buf`
    auto issue = [&](int buf, int slab){
        const float* Ap = Abase + slab*32;
        #pragma unroll
        for (int i=0;i<8;i++)
            cpa16(&sm->As[buf][t][4*i], Ap + 4*i);
        const float* Bp = Bbase + (size_t)slab*32*N;
        #pragma unroll
        for (int j=0;j<4;j++)
            cpa16(&sm->Bs[buf][brow][bcol4 + 16*j], Bp + 16*j);
    };

    issue(0, 0);
    CP_COMMIT();

    int nslab = K >> 5;
    for (int s=0; s<nslab; s++){
        int buf = s & 1;
        CP_WAIT0();                 // slab s landed (only its group outstanding)
        __syncthreads();            // visibility + all warps done with buf^1
        if (s + 1 < nslab){
            issue(buf ^ 1, s + 1);  // overlaps with compute of slab s
            CP_COMMIT();
        }
        #pragma unroll
        for (int ks=0; ks<4; ks++){
            int kk = ks*8;
            unsigned af[4][4], bf[4][2];
            #pragma unroll
            for (int mt=0; mt<4; mt++){
                int m = wm*64 + mt*16;
                af[mt][0] = __float_as_uint(sm->As[buf][m+g  ][kk+tig  ]);
                af[mt][1] = __float_as_uint(sm->As[buf][m+g+8][kk+tig  ]);
                af[mt][2] = __float_as_uint(sm->As[buf][m+g  ][kk+tig+4]);
                af[mt][3] = __float_as_uint(sm->As[buf][m+g+8][kk+tig+4]);
            }
            #pragma unroll
            for (int nt=0; nt<4; nt++){
                int n = wn*32 + nt*8;
                bf[nt][0] = __float_as_uint(sm->Bs[buf][kk+tig  ][n+g]);
                bf[nt][1] = __float_as_uint(sm->Bs[buf][kk+tig+4][n+g]);
            }
            #pragma unroll
            for (int mt=0; mt<4; mt++)
            #pragma unroll
            for (int nt=0; nt<4; nt++)
                mma8(acc[mt][nt], af[mt], bf[nt]);
        }
    }

    // ---------------- epilogue (float2 per half-fragment) --------------
    #pragma unroll
    for (int mt=0; mt<4; mt++){
        #pragma unroll
        for (int nt=0; nt<4; nt++){
            int col = n0 + wn*32 + nt*8 + 2*tig;
            #pragma unroll
            for (int hh=0; hh<2; hh++){
                int row = m0 + wm*64 + mt*16 + g + hh*8;
                float2 v = make_float2(acc[mt][nt][hh*2+0], acc[mt][nt][hh*2+1]);
                if (EPI == 0){
                    *(float2*)(C + (size_t)row*N + col) = v;
                } else if (EPI == 1){
                    float2 bb = *(const float2*)(bias + col);
                    float2 rr = *(const float2*)(res + (size_t)row*N + col);
                    v.x += bb.x + rr.x; v.y += bb.y + rr.y;
                    *(float2*)(C + (size_t)row*N + col) = v;
                } else if (EPI == 2){
                    float2 bb = *(const float2*)(bias + col);
                    v.x = tf32r(gelu_fast(v.x + bb.x));
                    v.y = tf32r(gelu_fast(v.y + bb.y));
                    *(float2*)(C + (size_t)row*N + col) = v;
                } else {
                    int which = col >> 10;
                    int h = (col >> 6) & (NH-1);
                    int d = col & (HD-1);
                    int b = row >> 11;
                    int sg = row & (SEQ-1);
                    float* o = (which==0) ? Oq : ((which==1) ? Ok : Ov);
                    *(float2*)(o + ((size_t)((b*NH + h)*SEQ + sg))*HD + d) = v;
                }
            }
        }
    }
}

// ---------------- Flash attention (TF32 mma, causal) ------------------------
// 64-query tile, 64-key steps, 128 threads / 4 warps; warp w owns query rows
// [w*16, w*16+16): softmax row stats warp-local, P warp-private.
struct FlashSmemT {
    float Qs[64][68];
    float Ks[64][68];
    float Vs[64][72];
    float Ps[64][68];
};
extern __shared__ char flash_dyn[];

__global__ __launch_bounds__(128) void flash_tc_kernel(
    const float* __restrict__ Q, const float* __restrict__ K,
    const float* __restrict__ V, float* __restrict__ ctx)
{
    FlashSmemT* sm = (FlashSmemT*)flash_dyn;
    int t = threadIdx.x;
    int lane = t & 31, w = t >> 5;
    int g = lane >> 2, tig = lane & 3;
    int qb = blockIdx.x, bh = blockIdx.y;
    int mw = w * 16;

    const float* Qb = Q + ((size_t)bh*SEQ + (size_t)qb*64)*HD;
    const float* Kb = K + (size_t)bh*SEQ*HD;
    const float* Vb = V + (size_t)bh*SEQ*HD;

    #pragma unroll
    for (int i=0;i<8;i++){
        int cidx = t + 128*i;
        int r = cidx >> 4, c = (cidx & 15) * 4;
        float4 v = *(const float4*)(Qb + r*HD + c);
        sm->Qs[r][c+0] = tf32r(v.x*0.125f);
        sm->Qs[r][c+1] = tf32r(v.y*0.125f);
        sm->Qs[r][c+2] = tf32r(v.z*0.125f);
        sm->Qs[r][c+3] = tf32r(v.w*0.125f);
    }

    float m0 = -1e30f, m1 = -1e30f, l0 = 0.0f, l1 = 0.0f;
    float acc_o[8][4];
    #pragma unroll
    for (int nt=0; nt<8; nt++)
    #pragma unroll
    for (int r=0; r<4; r++) acc_o[nt][r] = 0.0f;

    for (int jt=0; jt<=qb; jt++){
        __syncthreads();
        const float* Kp = Kb + (size_t)jt*64*HD;
        const float* Vp = Vb + (size_t)jt*64*HD;
        #pragma unroll
        for (int i=0;i<8;i++){
            int cidx = t + 128*i;
            int r = cidx >> 4, c = (cidx & 15) * 4;
            float4 kv = *(const float4*)(Kp + r*HD + c);
            sm->Ks[r][c+0] = tf32r(kv.x); sm->Ks[r][c+1] = tf32r(kv.y);
            sm->Ks[r][c+2] = tf32r(kv.z); sm->Ks[r][c+3] = tf32r(kv.w);
            float4 vv = *(const float4*)(Vp + r*HD + c);
            sm->Vs[r][c+0] = tf32r(vv.x); sm->Vs[r][c+1] = tf32r(vv.y);
            sm->Vs[r][c+2] = tf32r(vv.z); sm->Vs[r][c+3] = tf32r(vv.w);
        }
        __syncthreads();

        float acc_s[8][4];
        #pragma unroll
        for (int nt=0; nt<8; nt++)
        #pragma unroll
        for (int r=0; r<4; r++) acc_s[nt][r] = 0.0f;
        #pragma unroll
        for (int ks=0; ks<8; ks++){
            int kk = ks*8;
            unsigned af[4];
            af[0] = __float_as_uint(sm->Qs[mw+g  ][kk+tig  ]);
            af[1] = __float_as_uint(sm->Qs[mw+g+8][kk+tig  ]);
            af[2] = __float_as_uint(sm->Qs[mw+g  ][kk+tig+4]);
            af[3] = __float_as_uint(sm->Qs[mw+g+8][kk+tig+4]);
            #pragma unroll
            for (int nt=0; nt<8; nt++){
                unsigned bf[2];
                bf[0] = __float_as_uint(sm->Ks[nt*8+g][kk+tig  ]);
                bf[1] = __float_as_uint(sm->Ks[nt*8+g][kk+tig+4]);
                mma8(acc_s[nt], af, bf);
            }
        }

        if (jt == qb){
            int i0 = mw + g;
            #pragma unroll
            for (int nt=0; nt<8; nt++){
                int j = nt*8 + 2*tig;
                if (j   > i0)   acc_s[nt][0] = -1e30f;
                if (j+1 > i0)   acc_s[nt][1] = -1e30f;
                if (j   > i0+8) acc_s[nt][2] = -1e30f;
                if (j+1 > i0+8) acc_s[nt][3] = -1e30f;
            }
        }

        float mx0 = -1e30f, mx1 = -1e30f;
        #pragma unroll
        for (int nt=0; nt<8; nt++){
            mx0 = fmaxf(mx0, fmaxf(acc_s[nt][0], acc_s[nt][1]));
            mx1 = fmaxf(mx1, fmaxf(acc_s[nt][2], acc_s[nt][3]));
        }
        mx0 = fmaxf(mx0, __shfl_xor_sync(0xffffffffu, mx0, 1));
        mx0 = fmaxf(mx0, __shfl_xor_sync(0xffffffffu, mx0, 2));
        mx1 = fmaxf(mx1, __shfl_xor_sync(0xffffffffu, mx1, 1));
        mx1 = fmaxf(mx1, __shfl_xor_sync(0xffffffffu, mx1, 2));
        float mn0 = fmaxf(m0, mx0), mn1 = fmaxf(m1, mx1);
        float al0 = __expf(m0 - mn0), al1 = __expf(m1 - mn1);
        float s0 = 0.0f, s1 = 0.0f;
        #pragma unroll
        for (int nt=0; nt<8; nt++){
            float p00 = __expf(acc_s[nt][0] - mn0);
            float p01 = __expf(acc_s[nt][1] - mn0);
            float p10 = __expf(acc_s[nt][2] - mn1);
            float p11 = __expf(acc_s[nt][3] - mn1);
            s0 += p00 + p01; s1 += p10 + p11;
            *(float2*)&sm->Ps[mw+g  ][nt*8 + 2*tig] = make_float2(tf32r(p00), tf32r(p01));
            *(float2*)&sm->Ps[mw+g+8][nt*8 + 2*tig] = make_float2(tf32r(p10), tf32r(p11));
        }
        s0 += __shfl_xor_sync(0xffffffffu, s0, 1);
        s0 += __shfl_xor_sync(0xffffffffu, s0, 2);
        s1 += __shfl_xor_sync(0xffffffffu, s1, 1);
        s1 += __shfl_xor_sync(0xffffffffu, s1, 2);
        m0 = mn0; m1 = mn1;
        l0 = l0*al0 + s0; l1 = l1*al1 + s1;
        #pragma unroll
        for (int nt=0; nt<8; nt++){
            acc_o[nt][0] *= al0; acc_o[nt][1] *= al0;
            acc_o[nt][2] *= al1; acc_o[nt][3] *= al1;
        }

        __syncwarp();

        #pragma unroll
        for (int ks=0; ks<8; ks++){
            int kk = ks*8;
            unsigned af[4];
            af[0] = __float_as_uint(sm->Ps[mw+g  ][kk+tig  ]);
            af[1] = __float_as_uint(sm->Ps[mw+g+8][kk+tig  ]);
            af[2] = __float_as_uint(sm->Ps[mw+g  ][kk+tig+4]);
            af[3] = __float_as_uint(sm->Ps[mw+g+8][kk+tig+4]);
            #pragma unroll
            for (int nt=0; nt<8; nt++){
                unsigned bf[2];
                bf[0] = __float_as_uint(sm->Vs[kk+tig  ][nt*8+g]);
                bf[1] = __float_as_uint(sm->Vs[kk+tig+4][nt*8+g]);
                mma8(acc_o[nt], af, bf);
            }
        }
    }

    // normalize, tf32-round (feeds Wout GEMM), write ctx in [B,S,D]
    float inv0 = 1.0f/l0, inv1 = 1.0f/l1;
    int b = bh >> 4, h = bh & (NH-1);
    int r0 = qb*64 + mw + g, r1 = r0 + 8;
    #pragma unroll
    for (int nt=0; nt<8; nt++){
        int col = h*HD + nt*8 + 2*tig;
        *(float2*)(ctx + (size_t)(b*SEQ + r0)*DMODEL + col) =
            make_float2(tf32r(acc_o[nt][0]*inv0), tf32r(acc_o[nt][1]*inv0));
        *(float2*)(ctx + (size_t)(b*SEQ + r1)*DMODEL + col) =
            make_float2(tf32r(acc_o[nt][2]*inv1), tf32r(acc_o[nt][3]*inv1));
    }
}

// ---------------- launch ----------------------------------------------------
extern "C" void kernel_launch(void* const* d_in, const int* in_sizes, int n_in,
                              void* d_out, int out_size)
{
    (void)in_sizes; (void)n_in; (void)out_size;
    const float* x    = (const float*)d_in[0];
    const float* Wqkv = (const float*)d_in[1];
    const float* Wout = (const float*)d_in[2];
    const float* bout = (const float*)d_in[3];
    const float* W1   = (const float*)d_in[4];
    const float* b1   = (const float*)d_in[5];
    const float* W2   = (const float*)d_in[6];
    const float* b2   = (const float*)d_in[7];
    const float* g1   = (const float*)d_in[8];
    const float* s1   = (const float*)d_in[9];
    const float* g2   = (const float*)d_in[10];
    const float* s2   = (const float*)d_in[11];
    float* out = (float*)d_out;

    float *p_ln, *p_q, *p_k, *p_v, *p_ctx, *p_x1, *p_h2;
    float *p_wqkvR, *p_woutR, *p_w1R, *p_w2R;
    cudaGetSymbolAddress((void**)&p_ln,  g_ln);
    cudaGetSymbolAddress((void**)&p_q,   g_q);
    cudaGetSymbolAddress((void**)&p_k,   g_k);
    cudaGetSymbolAddress((void**)&p_v,   g_v);
    cudaGetSymbolAddress((void**)&p_ctx, g_ctx);
    cudaGetSymbolAddress((void**)&p_x1,  g_x1);
    cudaGetSymbolAddress((void**)&p_h2,  g_h2);
    cudaGetSymbolAddress((void**)&p_wqkvR, g_wqkvR);
    cudaGetSymbolAddress((void**)&p_woutR, g_woutR);
    cudaGetSymbolAddress((void**)&p_w1R,   g_w1R);
    cudaGetSymbolAddress((void**)&p_w2R,   g_w2R);

    const int gsmem = (int)sizeof(GSmem);
    const int fsmem = (int)sizeof(FlashSmemT);
    cudaFuncSetAttribute(tfgemm_kernel<1>, cudaFuncAttributeMaxDynamicSharedMemorySize, gsmem);
    cudaFuncSetAttribute(tfgemm_kernel<2>, cudaFuncAttributeMaxDynamicSharedMemorySize, gsmem);
    cudaFuncSetAttribute(tfgemm_kernel<3>, cudaFuncAttributeMaxDynamicSharedMemorySize, gsmem);
    cudaFuncSetAttribute(flash_tc_kernel, cudaFuncAttributeMaxDynamicSharedMemorySize, fsmem);

    // 0) tf32 pre-round of all weights (once per launch; ~25us total)
    round_tf32_kernel<<<(DMODEL*3*DMODEL)/1024, 256>>>(Wqkv, p_wqkvR);
    round_tf32_kernel<<<(DMODEL*DMODEL)/1024,   256>>>(Wout, p_woutR);
    round_tf32_kernel<<<(DMODEL*DFF)/1024,      256>>>(W1,   p_w1R);
    round_tf32_kernel<<<(DFF*DMODEL)/1024,      256>>>(W2,   p_w2R);

    // 1) ln1 (rounds its output)
    ln_kernel<<<NTOK, 256>>>(x, g1, s1, p_ln);
    // 2) qkv gemm + scatter to [B,H,S,HD]
    tfgemm_kernel<3><<<dim3(3*DMODEL/64, NTOK/128), 128, gsmem>>>(
        p_ln, p_wqkvR, nullptr, nullptr, nullptr, p_q, p_k, p_v,
        NTOK, 3*DMODEL, DMODEL);
    // 3) causal flash attention (tensor cores; rounds ctx output)
    flash_tc_kernel<<<dim3(SEQ/64, NB*NH), 128, fsmem>>>(p_q, p_k, p_v, p_ctx);
    // 4) out proj + bias + residual(x)
    tfgemm_kernel<1><<<dim3(DMODEL/64, NTOK/128), 128, gsmem>>>(
        p_ctx, p_woutR, bout, x, p_x1, nullptr, nullptr, nullptr,
        NTOK, DMODEL, DMODEL);
    // 5) ln2 (rounds its output)
    ln_kernel<<<NTOK, 256>>>(p_x1, g2, s2, p_ln);
    // 6) W1 + bias + gelu (rounds its output)
    tfgemm_kernel<2><<<dim3(DFF/64, NTOK/128), 128, gsmem>>>(
        p_ln, p_w1R, b1, nullptr, p_h2, nullptr, nullptr, nullptr,
        NTOK, DFF, DMODEL);
    // 7) W2 + bias + residual(x1) -> out
    tfgemm_kernel<1><<<dim3(DMODEL/64, NTOK/128), 128, gsmem>>>(
        p_h2, p_w2R, b2, p_x1, out, nullptr, nullptr, nullptr,
        NTOK, DMODEL, DFF);
}

// round 14
// speedup vs baseline: 2.2333x; 1.8511x over previous
#include <cuda_runtime.h>
#include <cuda_fp16.h>
#include <math.h>
#include <stdint.h>

#define NB 4
#define SEQ 2048
#define DMODEL 1024
#define NH 16
#define HD 64
#define NTOK (NB*SEQ)      /* 8192 */
#define DFF 4096

// ---------------- scratch (device globals; no allocations allowed) ----------
__device__ __half g_ln [(size_t)NTOK*DMODEL];
__device__ float  g_q  [(size_t)NTOK*DMODEL];
__device__ float  g_k  [(size_t)NTOK*DMODEL];
__device__ float  g_v  [(size_t)NTOK*DMODEL];
__device__ __half g_ctx[(size_t)NTOK*DMODEL];
__device__ float  g_x1 [(size_t)NTOK*DMODEL];
__device__ __half g_h2 [(size_t)NTOK*DFF];
// fp16 transposed weights: Wt[n][k] = fp16(W[k][n])
__device__ __half g_wqkvT[(size_t)3*DMODEL*DMODEL];
__device__ __half g_woutT[(size_t)DMODEL*DMODEL];
__device__ __half g_w1T  [(size_t)DFF*DMODEL];
__device__ __half g_w2T  [(size_t)DMODEL*DFF];

// ---------------- helpers ----------------------------------------------------
__device__ __forceinline__ float tf32r(float x){
    unsigned u; asm("cvt.rna.tf32.f32 %0, %1;" : "=r"(u) : "f"(x));
    return __uint_as_float(u);
}
__device__ __forceinline__ float gelu_fast(float x){
    float u = 0.7978845608028654f*(x + 0.044715f*x*x*x);
    float th; asm("tanh.approx.f32 %0, %1;" : "=f"(th) : "f"(u));
    return 0.5f*x*(1.0f + th);
}
// fp16 tensor-core mma: D(16x8,f32) += A(16x16,f16,row) * B(16x8,f16,col)
__device__ __forceinline__ void mma16(float* c, const unsigned* a, const unsigned* b){
    asm volatile(
        "mma.sync.aligned.m16n8k16.row.col.f32.f16.f16.f32 "
        "{%0,%1,%2,%3}, {%4,%5,%6,%7}, {%8,%9}, {%0,%1,%2,%3};\n"
        : "+f"(c[0]), "+f"(c[1]), "+f"(c[2]), "+f"(c[3])
        : "r"(a[0]), "r"(a[1]), "r"(a[2]), "r"(a[3]), "r"(b[0]), "r"(b[1]));
}
// tf32 mma (flash kernel)
__device__ __forceinline__ void mma8(float* c, const unsigned* a, const unsigned* b){
    asm volatile(
        "mma.sync.aligned.m16n8k8.row.col.f32.tf32.tf32.f32 "
        "{%0,%1,%2,%3}, {%4,%5,%6,%7}, {%8,%9}, {%0,%1,%2,%3};\n"
        : "+f"(c[0]), "+f"(c[1]), "+f"(c[2]), "+f"(c[3])
        : "r"(a[0]), "r"(a[1]), "r"(a[2]), "r"(a[3]), "r"(b[0]), "r"(b[1]));
}
__device__ __forceinline__ void cpa16(void* smem_dst, const void* gsrc){
    unsigned d = (unsigned)__cvta_generic_to_shared(smem_dst);
    asm volatile("cp.async.cg.shared.global [%0], [%1], 16;\n" :: "r"(d), "l"(gsrc));
}
#define CP_COMMIT() asm volatile("cp.async.commit_group;\n" ::: "memory")
#define CP_WAIT0()  asm volatile("cp.async.wait_group 0;\n" ::: "memory")

// ---------------- weight transpose + fp16 convert -----------------------------
// dst[n][k] = fp16(src[k][n]); src is K x N row-major.
__global__ __launch_bounds__(256) void transh_kernel(
    const float* __restrict__ src, __half* __restrict__ dst, int K, int N)
{
    __shared__ float tile[32][33];
    int k0 = blockIdx.y*32, n0 = blockIdx.x*32;
    int tx = threadIdx.x & 31, ty = threadIdx.x >> 5;  // 32 x 8
    #pragma unroll
    for (int i=0;i<32;i+=8)
        tile[ty+i][tx] = src[(size_t)(k0+ty+i)*N + n0+tx];
    __syncthreads();
    #pragma unroll
    for (int i=0;i<32;i+=8)
        dst[(size_t)(n0+ty+i)*K + k0+tx] = __float2half_rn(tile[tx][ty+i]);
}

// ---------------- LayerNorm (fp16 output) ------------------------------------
__global__ __launch_bounds__(256) void ln_kernel(const float* __restrict__ x,
        const float* __restrict__ g, const float* __restrict__ s,
        __half* __restrict__ out)
{
    int row = blockIdx.x;
    int t = threadIdx.x;
    const float4* xr = (const float4*)(x + (size_t)row*DMODEL);
    float4 v = xr[t];
    float sum = v.x+v.y+v.z+v.w;
    float sq  = v.x*v.x+v.y*v.y+v.z*v.z+v.w*v.w;
    #pragma unroll
    for (int o=16;o>0;o>>=1){
        sum += __shfl_xor_sync(0xffffffffu, sum, o);
        sq  += __shfl_xor_sync(0xffffffffu, sq , o);
    }
    __shared__ float red[16];
    if ((t&31)==0){ red[t>>5] = sum; red[8+(t>>5)] = sq; }
    __syncthreads();
    sum = 0.0f; sq = 0.0f;
    #pragma unroll
    for (int w=0; w<8; w++){ sum += red[w]; sq += red[8+w]; }
    float mean = sum * (1.0f/DMODEL);
    float var  = sq  * (1.0f/DMODEL) - mean*mean;
    float rinv = rsqrtf(var + 1e-5f);
    float4 gv = ((const float4*)g)[t];
    float4 sv = ((const float4*)s)[t];
    __half2* orow = (__half2*)(out + (size_t)row*DMODEL);
    orow[2*t  ] = __floats2half2_rn((v.x-mean)*rinv*gv.x + sv.x,
                                    (v.y-mean)*rinv*gv.y + sv.y);
    orow[2*t+1] = __floats2half2_rn((v.z-mean)*rinv*gv.z + sv.z,
                                    (v.w-mean)*rinv*gv.w + sv.w);
}

// ---------------- FP16 tensor-core GEMM --------------------------------------
// C[M,N] (+eps) = A[M,K](f16) @ Bt[N,K](f16)^T. 128x128 CTA tile, 256 thr,
// 8 warps (2x4), warp tile 64x32 as 4x4 m16n8k16. K-slab 64 halfs (128B rows),
// R5-proven 2-stage cp.async double buffer, __launch_bounds__(256,2).
// Row stride 72 halfs -> every fragment lds.32 hits banks 4g+tig (conflict-free).
// EPI: 1 +bias+residual(f32 C), 2 +bias+gelu(f16 C), 3 qkv scatter(f32).
struct GSmemH {
    __half As[2][128][72];
    __half Bs[2][128][72];
};
extern __shared__ char gsm_raw[];

template<int EPI>
__global__ __launch_bounds__(256,2) void hgemm_kernel(
    const __half* __restrict__ A, const __half* __restrict__ Bt,
    const float* __restrict__ bias, const float* __restrict__ res,
    void* __restrict__ Cv,
    float* __restrict__ Oq, float* __restrict__ Ok, float* __restrict__ Ov,
    int M, int N, int K)
{
    GSmemH* sm = (GSmemH*)gsm_raw;
    int t = threadIdx.x;
    int lane = t & 31, w = t >> 5;
    int wm = w >> 2, wn = w & 3;        // warp grid 2 x 4
    int g = lane >> 2, tig = lane & 3;  // mma groupID / thread-in-group
    int m0 = blockIdx.y * 128, n0 = blockIdx.x * 128;

    // copy layout: 2 threads per 128-row, each owns 64B (4 x 16B chunks)
    const int crow = t >> 1, coff = (t & 1) * 32;   // halfs
    const __half* Ab = A  + (size_t)(m0 + crow)*K + coff;
    const __half* Bb = Bt + (size_t)(n0 + crow)*K + coff;

    float acc[4][4][4];
    #pragma unroll
    for (int i=0;i<4;i++)
    #pragma unroll
    for (int j=0;j<4;j++)
    #pragma unroll
    for (int r=0;r<4;r++) acc[i][j][r] = 0.0f;

    auto issue = [&](int buf, int slab){
        const __half* Ap = Ab + slab*64;
        const __half* Bp = Bb + slab*64;
        #pragma unroll
        for (int i=0;i<4;i++)
            cpa16(&sm->As[buf][crow][coff + 8*i], Ap + 8*i);
        #pragma unroll
        for (int i=0;i<4;i++)
            cpa16(&sm->Bs[buf][crow][coff + 8*i], Bp + 8*i);
    };

    issue(0, 0);
    CP_COMMIT();

    int nslab = K >> 6;
    for (int s=0; s<nslab; s++){
        int buf = s & 1;
        CP_WAIT0();                 // slab s landed
        __syncthreads();            // visibility + all warps done with buf^1
        if (s + 1 < nslab){
            issue(buf ^ 1, s + 1);  // overlaps with compute of slab s
            CP_COMMIT();
        }
        #pragma unroll
        for (int ks=0; ks<4; ks++){
            int kk = ks*16;
            unsigned af[4][4], bf[4][2];
            #pragma unroll
            for (int mt=0; mt<4; mt++){
                int m = wm*64 + mt*16;
                af[mt][0] = *(const unsigned*)&sm->As[buf][m+g  ][kk+2*tig  ];
                af[mt][1] = *(const unsigned*)&sm->As[buf][m+g+8][kk+2*tig  ];
                af[mt][2] = *(const unsigned*)&sm->As[buf][m+g  ][kk+2*tig+8];
                af[mt][3] = *(const unsigned*)&sm->As[buf][m+g+8][kk+2*tig+8];
            }
            #pragma unroll
            for (int nt=0; nt<4; nt++){
                int n = wn*32 + nt*8;
                bf[nt][0] = *(const unsigned*)&sm->Bs[buf][n+g][kk+2*tig  ];
                bf[nt][1] = *(const unsigned*)&sm->Bs[buf][n+g][kk+2*tig+8];
            }
            #pragma unroll
            for (int mt=0; mt<4; mt++)
            #pragma unroll
            for (int nt=0; nt<4; nt++)
                mma16(acc[mt][nt], af[mt], bf[nt]);
        }
    }

    // ---------------- epilogue (2 cols per half-fragment) ---------------
    #pragma unroll
    for (int mt=0; mt<4; mt++){
        #pragma unroll
        for (int nt=0; nt<4; nt++){
            int col = n0 + wn*32 + nt*8 + 2*tig;
            #pragma unroll
            for (int hh=0; hh<2; hh++){
                int row = m0 + wm*64 + mt*16 + g + hh*8;
                float vx = acc[mt][nt][hh*2+0], vy = acc[mt][nt][hh*2+1];
                if (EPI == 1){
                    float2 bb = *(const float2*)(bias + col);
                    float2 rr = *(const float2*)(res + (size_t)row*N + col);
                    float2 o = make_float2(vx + bb.x + rr.x, vy + bb.y + rr.y);
                    *(float2*)((float*)Cv + (size_t)row*N + col) = o;
                } else if (EPI == 2){
                    float2 bb = *(const float2*)(bias + col);
                    *(__half2*)((__half*)Cv + (size_t)row*N + col) =
                        __floats2half2_rn(gelu_fast(vx + bb.x), gelu_fast(vy + bb.y));
                } else {
                    int which = col >> 10;
                    int h = (col >> 6) & (NH-1);
                    int d = col & (HD-1);
                    int b = row >> 11;
                    int sg = row & (SEQ-1);
                    float* o = (which==0) ? Oq : ((which==1) ? Ok : Ov);
                    *(float2*)(o + ((size_t)((b*NH + h)*SEQ + sg))*HD + d) =
                        make_float2(vx, vy);
                }
            }
        }
    }
}

// ---------------- Flash attention (TF32 mma, causal; fp16 ctx out) -----------
struct FlashSmemT {
    float Qs[64][68];
    float Ks[64][68];
    float Vs[64][72];
    float Ps[64][68];
};
extern __shared__ char flash_dyn[];

__global__ __launch_bounds__(128) void flash_tc_kernel(
    const float* __restrict__ Q, const float* __restrict__ K,
    const float* __restrict__ V, __half* __restrict__ ctx)
{
    FlashSmemT* sm = (FlashSmemT*)flash_dyn;
    int t = threadIdx.x;
    int lane = t & 31, w = t >> 5;
    int g = lane >> 2, tig = lane & 3;
    int qb = blockIdx.x, bh = blockIdx.y;
    int mw = w * 16;

    const float* Qb = Q + ((size_t)bh*SEQ + (size_t)qb*64)*HD;
    const float* Kb = K + (size_t)bh*SEQ*HD;
    const float* Vb = V + (size_t)bh*SEQ*HD;

    #pragma unroll
    for (int i=0;i<8;i++){
        int cidx = t + 128*i;
        int r = cidx >> 4, c = (cidx & 15) * 4;
        float4 v = *(const float4*)(Qb + r*HD + c);
        sm->Qs[r][c+0] = tf32r(v.x*0.125f);
        sm->Qs[r][c+1] = tf32r(v.y*0.125f);
        sm->Qs[r][c+2] = tf32r(v.z*0.125f);
        sm->Qs[r][c+3] = tf32r(v.w*0.125f);
    }

    float m0 = -1e30f, m1 = -1e30f, l0 = 0.0f, l1 = 0.0f;
    float acc_o[8][4];
    #pragma unroll
    for (int nt=0; nt<8; nt++)
    #pragma unroll
    for (int r=0; r<4; r++) acc_o[nt][r] = 0.0f;

    for (int jt=0; jt<=qb; jt++){
        __syncthreads();
        const float* Kp = Kb + (size_t)jt*64*HD;
        const float* Vp = Vb + (size_t)jt*64*HD;
        #pragma unroll
        for (int i=0;i<8;i++){
            int cidx = t + 128*i;
            int r = cidx >> 4, c = (cidx & 15) * 4;
            float4 kv = *(const float4*)(Kp + r*HD + c);
            sm->Ks[r][c+0] = tf32r(kv.x); sm->Ks[r][c+1] = tf32r(kv.y);
            sm->Ks[r][c+2] = tf32r(kv.z); sm->Ks[r][c+3] = tf32r(kv.w);
            float4 vv = *(const float4*)(Vp + r*HD + c);
            sm->Vs[r][c+0] = tf32r(vv.x); sm->Vs[r][c+1] = tf32r(vv.y);
            sm->Vs[r][c+2] = tf32r(vv.z); sm->Vs[r][c+3] = tf32r(vv.w);
        }
        __syncthreads();

        float acc_s[8][4];
        #pragma unroll
        for (int nt=0; nt<8; nt++)
        #pragma unroll
        for (int r=0; r<4; r++) acc_s[nt][r] = 0.0f;
        #pragma unroll
        for (int ks=0; ks<8; ks++){
            int kk = ks*8;
            unsigned af[4];
            af[0] = __float_as_uint(sm->Qs[mw+g  ][kk+tig  ]);
            af[1] = __float_as_uint(sm->Qs[mw+g+8][kk+tig  ]);
            af[2] = __float_as_uint(sm->Qs[mw+g  ][kk+tig+4]);
            af[3] = __float_as_uint(sm->Qs[mw+g+8][kk+tig+4]);
            #pragma unroll
            for (int nt=0; nt<8; nt++){
                unsigned bf[2];
                bf[0] = __float_as_uint(sm->Ks[nt*8+g][kk+tig  ]);
                bf[1] = __float_as_uint(sm->Ks[nt*8+g][kk+tig+4]);
                mma8(acc_s[nt], af, bf);
            }
        }

        if (jt == qb){
            int i0 = mw + g;
            #pragma unroll
            for (int nt=0; nt<8; nt++){
                int j = nt*8 + 2*tig;
                if (j   > i0)   acc_s[nt][0] = -1e30f;
                if (j+1 > i0)   acc_s[nt][1] = -1e30f;
                if (j   > i0+8) acc_s[nt][2] = -1e30f;
                if (j+1 > i0+8) acc_s[nt][3] = -1e30f;
            }
        }

        float mx0 = -1e30f, mx1 = -1e30f;
        #pragma unroll
        for (int nt=0; nt<8; nt++){
            mx0 = fmaxf(mx0, fmaxf(acc_s[nt][0], acc_s[nt][1]));
            mx1 = fmaxf(mx1, fmaxf(acc_s[nt][2], acc_s[nt][3]));
        }
        mx0 = fmaxf(mx0, __shfl_xor_sync(0xffffffffu, mx0, 1));
        mx0 = fmaxf(mx0, __shfl_xor_sync(0xffffffffu, mx0, 2));
        mx1 = fmaxf(mx1, __shfl_xor_sync(0xffffffffu, mx1, 1));
        mx1 = fmaxf(mx1, __shfl_xor_sync(0xffffffffu, mx1, 2));
        float mn0 = fmaxf(m0, mx0), mn1 = fmaxf(m1, mx1);
        float al0 = __expf(m0 - mn0), al1 = __expf(m1 - mn1);
        float s0 = 0.0f, s1 = 0.0f;
        #pragma unroll
        for (int nt=0; nt<8; nt++){
            float p00 = __expf(acc_s[nt][0] - mn0);
            float p01 = __expf(acc_s[nt][1] - mn0);
            float p10 = __expf(acc_s[nt][2] - mn1);
            float p11 = __expf(acc_s[nt][3] - mn1);
            s0 += p00 + p01; s1 += p10 + p11;
            *(float2*)&sm->Ps[mw+g  ][nt*8 + 2*tig] = make_float2(tf32r(p00), tf32r(p01));
            *(float2*)&sm->Ps[mw+g+8][nt*8 + 2*tig] = make_float2(tf32r(p10), tf32r(p11));
        }
        s0 += __shfl_xor_sync(0xffffffffu, s0, 1);
        s0 += __shfl_xor_sync(0xffffffffu, s0, 2);
        s1 += __shfl_xor_sync(0xffffffffu, s1, 1);
        s1 += __shfl_xor_sync(0xffffffffu, s1, 2);
        m0 = mn0; m1 = mn1;
        l0 = l0*al0 + s0; l1 = l1*al1 + s1;
        #pragma unroll
        for (int nt=0; nt<8; nt++){
            acc_o[nt][0] *= al0; acc_o[nt][1] *= al0;
            acc_o[nt][2] *= al1; acc_o[nt][3] *= al1;
        }

        __syncwarp();

        #pragma unroll
        for (int ks=0; ks<8; ks++){
            int kk = ks*8;
            unsigned af[4];
            af[0] = __float_as_uint(sm->Ps[mw+g  ][kk+tig  ]);
            af[1] = __float_as_uint(sm->Ps[mw+g+8][kk+tig  ]);
            af[2] = __float_as_uint(sm->Ps[mw+g  ][kk+tig+4]);
            af[3] = __float_as_uint(sm->Ps[mw+g+8][kk+tig+4]);
            #pragma unroll
            for (int nt=0; nt<8; nt++){
                unsigned bf[2];
                bf[0] = __float_as_uint(sm->Vs[kk+tig  ][nt*8+g]);
                bf[1] = __float_as_uint(sm->Vs[kk+tig+4][nt*8+g]);
                mma8(acc_o[nt], af, bf);
            }
        }
    }

    // normalize, write fp16 ctx in [B,S,D] (feeds Wout GEMM A operand)
    float inv0 = 1.0f/l0, inv1 = 1.0f/l1;
    int b = bh >> 4, h = bh & (NH-1);
    int r0 = qb*64 + mw + g, r1 = r0 + 8;
    #pragma unroll
    for (int nt=0; nt<8; nt++){
        int col = h*HD + nt*8 + 2*tig;
        *(__half2*)(ctx + (size_t)(b*SEQ + r0)*DMODEL + col) =
            __floats2half2_rn(acc_o[nt][0]*inv0, acc_o[nt][1]*inv0);
        *(__half2*)(ctx + (size_t)(b*SEQ + r1)*DMODEL + col) =
            __floats2half2_rn(acc_o[nt][2]*inv1, acc_o[nt][3]*inv1);
    }
}

// ---------------- launch ----------------------------------------------------
extern "C" void kernel_launch(void* const* d_in, const int* in_sizes, int n_in,
                              void* d_out, int out_size)
{
    (void)in_sizes; (void)n_in; (void)out_size;
    const float* x    = (const float*)d_in[0];
    const float* Wqkv = (const float*)d_in[1];
    const float* Wout = (const float*)d_in[2];
    const float* bout = (const float*)d_in[3];
    const float* W1   = (const float*)d_in[4];
    const float* b1   = (const float*)d_in[5];
    const float* W2   = (const float*)d_in[6];
    const float* b2   = (const float*)d_in[7];
    const float* g1   = (const float*)d_in[8];
    const float* s1   = (const float*)d_in[9];
    const float* g2   = (const float*)d_in[10];
    const float* s2   = (const float*)d_in[11];
    float* out = (float*)d_out;

    __half *p_ln, *p_ctx, *p_h2, *p_wqkvT, *p_woutT, *p_w1T, *p_w2T;
    float *p_q, *p_k, *p_v, *p_x1;
    cudaGetSymbolAddress((void**)&p_ln,  g_ln);
    cudaGetSymbolAddress((void**)&p_q,   g_q);
    cudaGetSymbolAddress((void**)&p_k,   g_k);
    cudaGetSymbolAddress((void**)&p_v,   g_v);
    cudaGetSymbolAddress((void**)&p_ctx, g_ctx);
    cudaGetSymbolAddress((void**)&p_x1,  g_x1);
    cudaGetSymbolAddress((void**)&p_h2,  g_h2);
    cudaGetSymbolAddress((void**)&p_wqkvT, g_wqkvT);
    cudaGetSymbolAddress((void**)&p_woutT, g_woutT);
    cudaGetSymbolAddress((void**)&p_w1T,   g_w1T);
    cudaGetSymbolAddress((void**)&p_w2T,   g_w2T);

    const int gsmem = (int)sizeof(GSmemH);
    const int fsmem = (int)sizeof(FlashSmemT);
    cudaFuncSetAttribute(hgemm_kernel<1>, cudaFuncAttributeMaxDynamicSharedMemorySize, gsmem);
    cudaFuncSetAttribute(hgemm_kernel<2>, cudaFuncAttributeMaxDynamicSharedMemorySize, gsmem);
    cudaFuncSetAttribute(hgemm_kernel<3>, cudaFuncAttributeMaxDynamicSharedMemorySize, gsmem);
    cudaFuncSetAttribute(flash_tc_kernel, cudaFuncAttributeMaxDynamicSharedMemorySize, fsmem);

    // 0) weight transpose + fp16 convert (once per launch; ~30us total)
    transh_kernel<<<dim3(3*DMODEL/32, DMODEL/32), 256>>>(Wqkv, p_wqkvT, DMODEL, 3*DMODEL);
    transh_kernel<<<dim3(DMODEL/32,   DMODEL/32), 256>>>(Wout, p_woutT, DMODEL, DMODEL);
    transh_kernel<<<dim3(DFF/32,      DMODEL/32), 256>>>(W1,   p_w1T,   DMODEL, DFF);
    transh_kernel<<<dim3(DMODEL/32,   DFF/32),    256>>>(W2,   p_w2T,   DFF,    DMODEL);

    // 1) ln1 -> fp16
    ln_kernel<<<NTOK, 256>>>(x, g1, s1, p_ln);
    // 2) qkv gemm (fp16 mma) + scatter to f32 [B,H,S,HD]
    hgemm_kernel<3><<<dim3(3*DMODEL/128, NTOK/128), 256, gsmem>>>(
        p_ln, p_wqkvT, nullptr, nullptr, nullptr, p_q, p_k, p_v,
        NTOK, 3*DMODEL, DMODEL);
    // 3) causal flash attention (tf32 mma; fp16 ctx out)
    flash_tc_kernel<<<dim3(SEQ/64, NB*NH), 128, fsmem>>>(p_q, p_k, p_v, p_ctx);
    // 4) out proj + bias + residual(x) -> f32 x1
    hgemm_kernel<1><<<dim3(DMODEL/128, NTOK/128), 256, gsmem>>>(
        p_ctx, p_woutT, bout, x, p_x1, nullptr, nullptr, nullptr,
        NTOK, DMODEL, DMODEL);
    // 5) ln2 -> fp16
    ln_kernel<<<NTOK, 256>>>(p_x1, g2, s2, p_ln);
    // 6) W1 + bias + gelu -> fp16 h2
    hgemm_kernel<2><<<dim3(DFF/128, NTOK/128), 256, gsmem>>>(
        p_ln, p_w1T, b1, nullptr, p_h2, nullptr, nullptr, nullptr,
        NTOK, DFF, DMODEL);
    // 7) W2 + bias + residual(x1) -> f32 out
    hgemm_kernel<1><<<dim3(DMODEL/128, NTOK/128), 256, gsmem>>>(
        p_h2, p_w2T, b2, p_x1, out, nullptr, nullptr, nullptr,
        NTOK, DMODEL, DFF);
}

// round 15
// speedup vs baseline: 2.2889x; 1.0249x over previous
#include <cuda_runtime.h>
#include <cuda_fp16.h>
#include <math.h>
#include <stdint.h>

#define NB 4
#define SEQ 2048
#define DMODEL 1024
#define NH 16
#define HD 64
#define NTOK (NB*SEQ)      /* 8192 */
#define DFF 4096

// ---------------- scratch (device globals; no allocations allowed) ----------
__device__ __half g_ln [(size_t)NTOK*DMODEL];
__device__ __half g_q  [(size_t)NTOK*DMODEL];
__device__ __half g_k  [(size_t)NTOK*DMODEL];
__device__ __half g_v  [(size_t)NTOK*DMODEL];
__device__ __half g_ctx[(size_t)NTOK*DMODEL];
__device__ float  g_x1 [(size_t)NTOK*DMODEL];
__device__ __half g_h2 [(size_t)NTOK*DFF];
// fp16 transposed weights: Wt[n][k] = fp16(W[k][n])
__device__ __half g_wqkvT[(size_t)3*DMODEL*DMODEL];
__device__ __half g_woutT[(size_t)DMODEL*DMODEL];
__device__ __half g_w1T  [(size_t)DFF*DMODEL];
__device__ __half g_w2T  [(size_t)DMODEL*DFF];

// ---------------- helpers ----------------------------------------------------
__device__ __forceinline__ float gelu_fast(float x){
    float u = 0.7978845608028654f*(x + 0.044715f*x*x*x);
    float th; asm("tanh.approx.f32 %0, %1;" : "=f"(th) : "f"(u));
    return 0.5f*x*(1.0f + th);
}
// fp16 tensor-core mma: D(16x8,f32) += A(16x16,f16,row) * B(16x8,f16,col)
__device__ __forceinline__ void mma16(float* c, const unsigned* a, const unsigned* b){
    asm volatile(
        "mma.sync.aligned.m16n8k16.row.col.f32.f16.f16.f32 "
        "{%0,%1,%2,%3}, {%4,%5,%6,%7}, {%8,%9}, {%0,%1,%2,%3};\n"
        : "+f"(c[0]), "+f"(c[1]), "+f"(c[2]), "+f"(c[3])
        : "r"(a[0]), "r"(a[1]), "r"(a[2]), "r"(a[3]), "r"(b[0]), "r"(b[1]));
}
__device__ __forceinline__ void cpa16(void* smem_dst, const void* gsrc){
    unsigned d = (unsigned)__cvta_generic_to_shared(smem_dst);
    asm volatile("cp.async.cg.shared.global [%0], [%1], 16;\n" :: "r"(d), "l"(gsrc));
}
#define CP_COMMIT() asm volatile("cp.async.commit_group;\n" ::: "memory")
#define CP_WAIT0()  asm volatile("cp.async.wait_group 0;\n" ::: "memory")

// ---------------- weight transpose + fp16 convert -----------------------------
__global__ __launch_bounds__(256) void transh_kernel(
    const float* __restrict__ src, __half* __restrict__ dst, int K, int N)
{
    __shared__ float tile[32][33];
    int k0 = blockIdx.y*32, n0 = blockIdx.x*32;
    int tx = threadIdx.x & 31, ty = threadIdx.x >> 5;  // 32 x 8
    #pragma unroll
    for (int i=0;i<32;i+=8)
        tile[ty+i][tx] = src[(size_t)(k0+ty+i)*N + n0+tx];
    __syncthreads();
    #pragma unroll
    for (int i=0;i<32;i+=8)
        dst[(size_t)(n0+ty+i)*K + k0+tx] = __float2half_rn(tile[tx][ty+i]);
}

// ---------------- LayerNorm (fp16 output) ------------------------------------
__global__ __launch_bounds__(256) void ln_kernel(const float* __restrict__ x,
        const float* __restrict__ g, const float* __restrict__ s,
        __half* __restrict__ out)
{
    int row = blockIdx.x;
    int t = threadIdx.x;
    const float4* xr = (const float4*)(x + (size_t)row*DMODEL);
    float4 v = xr[t];
    float sum = v.x+v.y+v.z+v.w;
    float sq  = v.x*v.x+v.y*v.y+v.z*v.z+v.w*v.w;
    #pragma unroll
    for (int o=16;o>0;o>>=1){
        sum += __shfl_xor_sync(0xffffffffu, sum, o);
        sq  += __shfl_xor_sync(0xffffffffu, sq , o);
    }
    __shared__ float red[16];
    if ((t&31)==0){ red[t>>5] = sum; red[8+(t>>5)] = sq; }
    __syncthreads();
    sum = 0.0f; sq = 0.0f;
    #pragma unroll
    for (int w=0; w<8; w++){ sum += red[w]; sq += red[8+w]; }
    float mean = sum * (1.0f/DMODEL);
    float var  = sq  * (1.0f/DMODEL) - mean*mean;
    float rinv = rsqrtf(var + 1e-5f);
    float4 gv = ((const float4*)g)[t];
    float4 sv = ((const float4*)s)[t];
    __half2* orow = (__half2*)(out + (size_t)row*DMODEL);
    orow[2*t  ] = __floats2half2_rn((v.x-mean)*rinv*gv.x + sv.x,
                                    (v.y-mean)*rinv*gv.y + sv.y);
    orow[2*t+1] = __floats2half2_rn((v.z-mean)*rinv*gv.z + sv.z,
                                    (v.w-mean)*rinv*gv.w + sv.w);
}

// ---------------- FP16 tensor-core GEMM (R13-proven) -------------------------
// 128x128 CTA tile, 256 thr, 8 warps (2x4), warp tile 64x32 as 4x4 m16n8k16.
// K-slab 64 halfs, 2-stage cp.async double buffer, bounds(256,2).
// EPI: 1 +bias+residual(f32 C), 2 +bias+gelu(f16 C), 3 qkv scatter(f16).
struct GSmemH {
    __half As[2][128][72];
    __half Bs[2][128][72];
};
extern __shared__ char gsm_raw[];

template<int EPI>
__global__ __launch_bounds__(256,2) void hgemm_kernel(
    const __half* __restrict__ A, const __half* __restrict__ Bt,
    const float* __restrict__ bias, const float* __restrict__ res,
    void* __restrict__ Cv,
    __half* __restrict__ Oq, __half* __restrict__ Ok, __half* __restrict__ Ov,
    int M, int N, int K)
{
    GSmemH* sm = (GSmemH*)gsm_raw;
    int t = threadIdx.x;
    int lane = t & 31, w = t >> 5;
    int wm = w >> 2, wn = w & 3;        // warp grid 2 x 4
    int g = lane >> 2, tig = lane & 3;  // mma groupID / thread-in-group
    int m0 = blockIdx.y * 128, n0 = blockIdx.x * 128;

    const int crow = t >> 1, coff = (t & 1) * 32;   // halfs
    const __half* Ab = A  + (size_t)(m0 + crow)*K + coff;
    const __half* Bb = Bt + (size_t)(n0 + crow)*K + coff;

    float acc[4][4][4];
    #pragma unroll
    for (int i=0;i<4;i++)
    #pragma unroll
    for (int j=0;j<4;j++)
    #pragma unroll
    for (int r=0;r<4;r++) acc[i][j][r] = 0.0f;

    auto issue = [&](int buf, int slab){
        const __half* Ap = Ab + slab*64;
        const __half* Bp = Bb + slab*64;
        #pragma unroll
        for (int i=0;i<4;i++)
            cpa16(&sm->As[buf][crow][coff + 8*i], Ap + 8*i);
        #pragma unroll
        for (int i=0;i<4;i++)
            cpa16(&sm->Bs[buf][crow][coff + 8*i], Bp + 8*i);
    };

    issue(0, 0);
    CP_COMMIT();

    int nslab = K >> 6;
    for (int s=0; s<nslab; s++){
        int buf = s & 1;
        CP_WAIT0();
        __syncthreads();
        if (s + 1 < nslab){
            issue(buf ^ 1, s + 1);
            CP_COMMIT();
        }
        #pragma unroll
        for (int ks=0; ks<4; ks++){
            int kk = ks*16;
            unsigned af[4][4], bf[4][2];
            #pragma unroll
            for (int mt=0; mt<4; mt++){
                int m = wm*64 + mt*16;
                af[mt][0] = *(const unsigned*)&sm->As[buf][m+g  ][kk+2*tig  ];
                af[mt][1] = *(const unsigned*)&sm->As[buf][m+g+8][kk+2*tig  ];
                af[mt][2] = *(const unsigned*)&sm->As[buf][m+g  ][kk+2*tig+8];
                af[mt][3] = *(const unsigned*)&sm->As[buf][m+g+8][kk+2*tig+8];
            }
            #pragma unroll
            for (int nt=0; nt<4; nt++){
                int n = wn*32 + nt*8;
                bf[nt][0] = *(const unsigned*)&sm->Bs[buf][n+g][kk+2*tig  ];
                bf[nt][1] = *(const unsigned*)&sm->Bs[buf][n+g][kk+2*tig+8];
            }
            #pragma unroll
            for (int mt=0; mt<4; mt++)
            #pragma unroll
            for (int nt=0; nt<4; nt++)
                mma16(acc[mt][nt], af[mt], bf[nt]);
        }
    }

    // ---------------- epilogue ---------------
    #pragma unroll
    for (int mt=0; mt<4; mt++){
        #pragma unroll
        for (int nt=0; nt<4; nt++){
            int col = n0 + wn*32 + nt*8 + 2*tig;
            #pragma unroll
            for (int hh=0; hh<2; hh++){
                int row = m0 + wm*64 + mt*16 + g + hh*8;
                float vx = acc[mt][nt][hh*2+0], vy = acc[mt][nt][hh*2+1];
                if (EPI == 1){
                    float2 bb = *(const float2*)(bias + col);
                    float2 rr = *(const float2*)(res + (size_t)row*N + col);
                    *(float2*)((float*)Cv + (size_t)row*N + col) =
                        make_float2(vx + bb.x + rr.x, vy + bb.y + rr.y);
                } else if (EPI == 2){
                    float2 bb = *(const float2*)(bias + col);
                    *(__half2*)((__half*)Cv + (size_t)row*N + col) =
                        __floats2half2_rn(gelu_fast(vx + bb.x), gelu_fast(vy + bb.y));
                } else {
                    int which = col >> 10;
                    int h = (col >> 6) & (NH-1);
                    int d = col & (HD-1);
                    int b = row >> 11;
                    int sg = row & (SEQ-1);
                    __half* o = (which==0) ? Oq : ((which==1) ? Ok : Ov);
                    *(__half2*)(o + ((size_t)((b*NH + h)*SEQ + sg))*HD + d) =
                        __floats2half2_rn(vx, vy);
                }
            }
        }
    }
}

// ---------------- Flash attention (FP16 mma, causal) -------------------------
// 64-query tile, 64-key steps, 128 threads / 4 warps; warp w owns query rows
// [w*16, w*16+16). Q/K/V/P in fp16 smem; V stored transposed (Vt[d][key]) so
// both QK^T and PV are m16n8k16 with contiguous lds.32 fragments.
// Row stride 72 halfs (144B): fragment banks 4g+tig, conflict-free.
struct FlashSmemH {
    __half Qs[64][72];
    __half Ks[64][72];
    __half Vt[64][72];   // [d][key]
    __half Ps[64][72];
};
extern __shared__ char flash_dyn[];

__global__ __launch_bounds__(128) void flash_h_kernel(
    const __half* __restrict__ Q, const __half* __restrict__ K,
    const __half* __restrict__ V, __half* __restrict__ ctx)
{
    FlashSmemH* sm = (FlashSmemH*)flash_dyn;
    int t = threadIdx.x;
    int lane = t & 31, w = t >> 5;
    int g = lane >> 2, tig = lane & 3;
    int qb = blockIdx.x, bh = blockIdx.y;
    int mw = w * 16;

    const __half* Qb = Q + ((size_t)bh*SEQ + (size_t)qb*64)*HD;
    const __half* Kb = K + (size_t)bh*SEQ*HD;
    const __half* Vb = V + (size_t)bh*SEQ*HD;

    // load Q tile, softmax scale folded (0.125 exact in fp16)
    {
        __half2 sc = __floats2half2_rn(0.125f, 0.125f);
        #pragma unroll
        for (int u=0; u<4; u++){
            int cidx = t + 128*u;           // 512 items of 8 halfs
            int r = cidx >> 3, c = (cidx & 7) * 8;
            uint4 v = *(const uint4*)(Qb + r*HD + c);
            __half2* pv = (__half2*)&v;
            pv[0]=__hmul2(pv[0],sc); pv[1]=__hmul2(pv[1],sc);
            pv[2]=__hmul2(pv[2],sc); pv[3]=__hmul2(pv[3],sc);
            *(uint4*)&sm->Qs[r][c] = v;
        }
    }

    float m0 = -1e30f, m1 = -1e30f, l0 = 0.0f, l1 = 0.0f;
    float acc_o[8][4];
    #pragma unroll
    for (int nt=0; nt<8; nt++)
    #pragma unroll
    for (int r=0; r<4; r++) acc_o[nt][r] = 0.0f;

    for (int jt=0; jt<=qb; jt++){
        __syncthreads();            // previous tile's reads of Ks/Vt done
        const __half* Kp = Kb + (size_t)jt*64*HD;
        const __half* Vp = Vb + (size_t)jt*64*HD;
        #pragma unroll
        for (int u=0; u<4; u++){
            int cidx = t + 128*u;
            int r = cidx >> 3, c = (cidx & 7) * 8;   // r = key, c = d chunk
            *(uint4*)&sm->Ks[r][c] = *(const uint4*)(Kp + r*HD + c);
            uint4 vv = *(const uint4*)(Vp + r*HD + c);
            const __half* vh = (const __half*)&vv;
            #pragma unroll
            for (int i=0;i<8;i++) sm->Vt[c+i][r] = vh[i];   // transpose
        }
        __syncthreads();

        // ---- S = Q @ K^T ----
        float acc_s[8][4];
        #pragma unroll
        for (int nt=0; nt<8; nt++)
        #pragma unroll
        for (int r=0; r<4; r++) acc_s[nt][r] = 0.0f;
        #pragma unroll
        for (int ks=0; ks<4; ks++){
            int kk = ks*16;
            unsigned af[4];
            af[0] = *(const unsigned*)&sm->Qs[mw+g  ][kk+2*tig  ];
            af[1] = *(const unsigned*)&sm->Qs[mw+g+8][kk+2*tig  ];
            af[2] = *(const unsigned*)&sm->Qs[mw+g  ][kk+2*tig+8];
            af[3] = *(const unsigned*)&sm->Qs[mw+g+8][kk+2*tig+8];
            #pragma unroll
            for (int nt=0; nt<8; nt++){
                unsigned bf[2];
                bf[0] = *(const unsigned*)&sm->Ks[nt*8+g][kk+2*tig  ];
                bf[1] = *(const unsigned*)&sm->Ks[nt*8+g][kk+2*tig+8];
                mma16(acc_s[nt], af, bf);
            }
        }

        // ---- causal mask on diagonal tile ----
        if (jt == qb){
            int i0 = mw + g;
            #pragma unroll
            for (int nt=0; nt<8; nt++){
                int j = nt*8 + 2*tig;
                if (j   > i0)   acc_s[nt][0] = -1e30f;
                if (j+1 > i0)   acc_s[nt][1] = -1e30f;
                if (j   > i0+8) acc_s[nt][2] = -1e30f;
                if (j+1 > i0+8) acc_s[nt][3] = -1e30f;
            }
        }

        // ---- online softmax (rows g, g+8; quad reduce) ----
        float mx0 = -1e30f, mx1 = -1e30f;
        #pragma unroll
        for (int nt=0; nt<8; nt++){
            mx0 = fmaxf(mx0, fmaxf(acc_s[nt][0], acc_s[nt][1]));
            mx1 = fmaxf(mx1, fmaxf(acc_s[nt][2], acc_s[nt][3]));
        }
        mx0 = fmaxf(mx0, __shfl_xor_sync(0xffffffffu, mx0, 1));
        mx0 = fmaxf(mx0, __shfl_xor_sync(0xffffffffu, mx0, 2));
        mx1 = fmaxf(mx1, __shfl_xor_sync(0xffffffffu, mx1, 1));
        mx1 = fmaxf(mx1, __shfl_xor_sync(0xffffffffu, mx1, 2));
        float mn0 = fmaxf(m0, mx0), mn1 = fmaxf(m1, mx1);
        float al0 = __expf(m0 - mn0), al1 = __expf(m1 - mn1);
        float s0 = 0.0f, s1 = 0.0f;
        #pragma unroll
        for (int nt=0; nt<8; nt++){
            float p00 = __expf(acc_s[nt][0] - mn0);
            float p01 = __expf(acc_s[nt][1] - mn0);
            float p10 = __expf(acc_s[nt][2] - mn1);
            float p11 = __expf(acc_s[nt][3] - mn1);
            s0 += p00 + p01; s1 += p10 + p11;
            *(__half2*)&sm->Ps[mw+g  ][nt*8 + 2*tig] = __floats2half2_rn(p00, p01);
            *(__half2*)&sm->Ps[mw+g+8][nt*8 + 2*tig] = __floats2half2_rn(p10, p11);
        }
        s0 += __shfl_xor_sync(0xffffffffu, s0, 1);
        s0 += __shfl_xor_sync(0xffffffffu, s0, 2);
        s1 += __shfl_xor_sync(0xffffffffu, s1, 1);
        s1 += __shfl_xor_sync(0xffffffffu, s1, 2);
        m0 = mn0; m1 = mn1;
        l0 = l0*al0 + s0; l1 = l1*al1 + s1;
        #pragma unroll
        for (int nt=0; nt<8; nt++){
            acc_o[nt][0] *= al0; acc_o[nt][1] *= al0;
            acc_o[nt][2] *= al1; acc_o[nt][3] *= al1;
        }

        __syncwarp();               // P visibility within owning warp

        // ---- O += P @ V  (B operand from Vt[d][key]) ----
        #pragma unroll
        for (int ks=0; ks<4; ks++){
            int kk = ks*16;
            unsigned af[4];
            af[0] = *(const unsigned*)&sm->Ps[mw+g  ][kk+2*tig  ];
            af[1] = *(const unsigned*)&sm->Ps[mw+g+8][kk+2*tig  ];
            af[2] = *(const unsigned*)&sm->Ps[mw+g  ][kk+2*tig+8];
            af[3] = *(const unsigned*)&sm->Ps[mw+g+8][kk+2*tig+8];
            #pragma unroll
            for (int nt=0; nt<8; nt++){
                unsigned bf[2];
                bf[0] = *(const unsigned*)&sm->Vt[nt*8+g][kk+2*tig  ];
                bf[1] = *(const unsigned*)&sm->Vt[nt*8+g][kk+2*tig+8];
                mma16(acc_o[nt], af, bf);
            }
        }
    }

    // normalize, write fp16 ctx in [B,S,D] (feeds Wout GEMM A operand)
    float inv0 = 1.0f/l0, inv1 = 1.0f/l1;
    int b = bh >> 4, h = bh & (NH-1);
    int r0 = qb*64 + mw + g, r1 = r0 + 8;
    #pragma unroll
    for (int nt=0; nt<8; nt++){
        int col = h*HD + nt*8 + 2*tig;
        *(__half2*)(ctx + (size_t)(b*SEQ + r0)*DMODEL + col) =
            __floats2half2_rn(acc_o[nt][0]*inv0, acc_o[nt][1]*inv0);
        *(__half2*)(ctx + (size_t)(b*SEQ + r1)*DMODEL + col) =
            __floats2half2_rn(acc_o[nt][2]*inv1, acc_o[nt][3]*inv1);
    }
}

// ---------------- launch ----------------------------------------------------
extern "C" void kernel_launch(void* const* d_in, const int* in_sizes, int n_in,
                              void* d_out, int out_size)
{
    (void)in_sizes; (void)n_in; (void)out_size;
    const float* x    = (const float*)d_in[0];
    const float* Wqkv = (const float*)d_in[1];
    const float* Wout = (const float*)d_in[2];
    const float* bout = (const float*)d_in[3];
    const float* W1   = (const float*)d_in[4];
    const float* b1   = (const float*)d_in[5];
    const float* W2   = (const float*)d_in[6];
    const float* b2   = (const float*)d_in[7];
    const float* g1   = (const float*)d_in[8];
    const float* s1   = (const float*)d_in[9];
    const float* g2   = (const float*)d_in[10];
    const float* s2   = (const float*)d_in[11];
    float* out = (float*)d_out;

    __half *p_ln, *p_q, *p_k, *p_v, *p_ctx, *p_h2;
    __half *p_wqkvT, *p_woutT, *p_w1T, *p_w2T;
    float *p_x1;
    cudaGetSymbolAddress((void**)&p_ln,  g_ln);
    cudaGetSymbolAddress((void**)&p_q,   g_q);
    cudaGetSymbolAddress((void**)&p_k,   g_k);
    cudaGetSymbolAddress((void**)&p_v,   g_v);
    cudaGetSymbolAddress((void**)&p_ctx, g_ctx);
    cudaGetSymbolAddress((void**)&p_x1,  g_x1);
    cudaGetSymbolAddress((void**)&p_h2,  g_h2);
    cudaGetSymbolAddress((void**)&p_wqkvT, g_wqkvT);
    cudaGetSymbolAddress((void**)&p_woutT, g_woutT);
    cudaGetSymbolAddress((void**)&p_w1T,   g_w1T);
    cudaGetSymbolAddress((void**)&p_w2T,   g_w2T);

    const int gsmem = (int)sizeof(GSmemH);
    const int fsmem = (int)sizeof(FlashSmemH);
    cudaFuncSetAttribute(hgemm_kernel<1>, cudaFuncAttributeMaxDynamicSharedMemorySize, gsmem);
    cudaFuncSetAttribute(hgemm_kernel<2>, cudaFuncAttributeMaxDynamicSharedMemorySize, gsmem);
    cudaFuncSetAttribute(hgemm_kernel<3>, cudaFuncAttributeMaxDynamicSharedMemorySize, gsmem);
    cudaFuncSetAttribute(flash_h_kernel, cudaFuncAttributeMaxDynamicSharedMemorySize, fsmem);

    // 0) weight transpose + fp16 convert (once per launch; ~30us total)
    transh_kernel<<<dim3(3*DMODEL/32, DMODEL/32), 256>>>(Wqkv, p_wqkvT, DMODEL, 3*DMODEL);
    transh_kernel<<<dim3(DMODEL/32,   DMODEL/32), 256>>>(Wout, p_woutT, DMODEL, DMODEL);
    transh_kernel<<<dim3(DFF/32,      DMODEL/32), 256>>>(W1,   p_w1T,   DMODEL, DFF);
    transh_kernel<<<dim3(DMODEL/32,   DFF/32),    256>>>(W2,   p_w2T,   DFF,    DMODEL);

    // 1) ln1 -> fp16
    ln_kernel<<<NTOK, 256>>>(x, g1, s1, p_ln);
    // 2) qkv gemm (fp16 mma) + scatter to fp16 [B,H,S,HD]
    hgemm_kernel<3><<<dim3(3*DMODEL/128, NTOK/128), 256, gsmem>>>(
        p_ln, p_wqkvT, nullptr, nullptr, nullptr, p_q, p_k, p_v,
        NTOK, 3*DMODEL, DMODEL);
    // 3) causal flash attention (fp16 mma; fp16 ctx out)
    flash_h_kernel<<<dim3(SEQ/64, NB*NH), 128, fsmem>>>(p_q, p_k, p_v, p_ctx);
    // 4) out proj + bias + residual(x) -> f32 x1
    hgemm_kernel<1><<<dim3(DMODEL/128, NTOK/128), 256, gsmem>>>(
        p_ctx, p_woutT, bout, x, p_x1, nullptr, nullptr, nullptr,
        NTOK, DMODEL, DMODEL);
    // 5) ln2 -> fp16
    ln_kernel<<<NTOK, 256>>>(p_x1, g2, s2, p_ln);
    // 6) W1 + bias + gelu -> fp16 h2
    hgemm_kernel<2><<<dim3(DFF/128, NTOK/128), 256, gsmem>>>(
        p_ln, p_w1T, b1, nullptr, p_h2, nullptr, nullptr, nullptr,
        NTOK, DFF, DMODEL);
    // 7) W2 + bias + residual(x1) -> f32 out
    hgemm_kernel<1><<<dim3(DMODEL/128, NTOK/128), 256, gsmem>>>(
        p_h2, p_w2T, b2, p_x1, out, nullptr, nullptr, nullptr,
        NTOK, DMODEL, DFF);
}

// round 16
// speedup vs baseline: 2.7408x; 1.1974x over previous
#include <cuda_runtime.h>
#include <cuda_fp16.h>
#include <math.h>
#include <stdint.h>

#define NB 4
#define SEQ 2048
#define DMODEL 1024
#define NH 16
#define HD 64
#define NTOK (NB*SEQ)      /* 8192 */
#define DFF 4096

// ---------------- scratch (device globals; no allocations allowed) ----------
__device__ __half g_ln [(size_t)NTOK*DMODEL];
__device__ __half g_q  [(size_t)NTOK*DMODEL];
__device__ __half g_k  [(size_t)NTOK*DMODEL];
__device__ __half g_v  [(size_t)NTOK*DMODEL];
__device__ __half g_ctx[(size_t)NTOK*DMODEL];
__device__ float  g_x1 [(size_t)NTOK*DMODEL];
__device__ __half g_h2 [(size_t)NTOK*DFF];
// fp16 transposed weights: Wt[n][k] = fp16(W[k][n])
__device__ __half g_wqkvT[(size_t)3*DMODEL*DMODEL];
__device__ __half g_woutT[(size_t)DMODEL*DMODEL];
__device__ __half g_w1T  [(size_t)DFF*DMODEL];
__device__ __half g_w2T  [(size_t)DMODEL*DFF];

// ---------------- helpers ----------------------------------------------------
__device__ __forceinline__ float gelu_fast(float x){
    float u = 0.7978845608028654f*(x + 0.044715f*x*x*x);
    float th; asm("tanh.approx.f32 %0, %1;" : "=f"(th) : "f"(u));
    return 0.5f*x*(1.0f + th);
}
__device__ __forceinline__ void mma16(float* c, const unsigned* a, const unsigned* b){
    asm volatile(
        "mma.sync.aligned.m16n8k16.row.col.f32.f16.f16.f32 "
        "{%0,%1,%2,%3}, {%4,%5,%6,%7}, {%8,%9}, {%0,%1,%2,%3};\n"
        : "+f"(c[0]), "+f"(c[1]), "+f"(c[2]), "+f"(c[3])
        : "r"(a[0]), "r"(a[1]), "r"(a[2]), "r"(a[3]), "r"(b[0]), "r"(b[1]));
}
__device__ __forceinline__ void ldsm_x4(unsigned* r, uint32_t addr){
    asm volatile("ldmatrix.sync.aligned.m8n8.x4.shared.b16 {%0,%1,%2,%3}, [%4];"
        : "=r"(r[0]), "=r"(r[1]), "=r"(r[2]), "=r"(r[3]) : "r"(addr));
}
__device__ __forceinline__ void ldsm_x2(unsigned* r, uint32_t addr){
    asm volatile("ldmatrix.sync.aligned.m8n8.x2.shared.b16 {%0,%1}, [%2];"
        : "=r"(r[0]), "=r"(r[1]) : "r"(addr));
}
__device__ __forceinline__ void ldsm_x2t(unsigned* r, uint32_t addr){
    asm volatile("ldmatrix.sync.aligned.m8n8.x2.trans.shared.b16 {%0,%1}, [%2];"
        : "=r"(r[0]), "=r"(r[1]) : "r"(addr));
}
__device__ __forceinline__ uint32_t smaddr(const void* p){
    return (uint32_t)__cvta_generic_to_shared(p);
}
__device__ __forceinline__ void cpa16(void* smem_dst, const void* gsrc){
    unsigned d = (unsigned)__cvta_generic_to_shared(smem_dst);
    asm volatile("cp.async.cg.shared.global [%0], [%1], 16;\n" :: "r"(d), "l"(gsrc));
}
#define CP_COMMIT() asm volatile("cp.async.commit_group;\n" ::: "memory")
#define CP_WAIT0()  asm volatile("cp.async.wait_group 0;\n" ::: "memory")

// ---------------- weight transpose + fp16 convert -----------------------------
__global__ __launch_bounds__(256) void transh_kernel(
    const float* __restrict__ src, __half* __restrict__ dst, int K, int N)
{
    __shared__ float tile[32][33];
    int k0 = blockIdx.y*32, n0 = blockIdx.x*32;
    int tx = threadIdx.x & 31, ty = threadIdx.x >> 5;  // 32 x 8
    #pragma unroll
    for (int i=0;i<32;i+=8)
        tile[ty+i][tx] = src[(size_t)(k0+ty+i)*N + n0+tx];
    __syncthreads();
    #pragma unroll
    for (int i=0;i<32;i+=8)
        dst[(size_t)(n0+ty+i)*K + k0+tx] = __float2half_rn(tile[tx][ty+i]);
}

// ---------------- LayerNorm (fp16 output) ------------------------------------
__global__ __launch_bounds__(256) void ln_kernel(const float* __restrict__ x,
        const float* __restrict__ g, const float* __restrict__ s,
        __half* __restrict__ out)
{
    int row = blockIdx.x;
    int t = threadIdx.x;
    const float4* xr = (const float4*)(x + (size_t)row*DMODEL);
    float4 v = xr[t];
    float sum = v.x+v.y+v.z+v.w;
    float sq  = v.x*v.x+v.y*v.y+v.z*v.z+v.w*v.w;
    #pragma unroll
    for (int o=16;o>0;o>>=1){
        sum += __shfl_xor_sync(0xffffffffu, sum, o);
        sq  += __shfl_xor_sync(0xffffffffu, sq , o);
    }
    __shared__ float red[16];
    if ((t&31)==0){ red[t>>5] = sum; red[8+(t>>5)] = sq; }
    __syncthreads();
    sum = 0.0f; sq = 0.0f;
    #pragma unroll
    for (int w=0; w<8; w++){ sum += red[w]; sq += red[8+w]; }
    float mean = sum * (1.0f/DMODEL);
    float var  = sq  * (1.0f/DMODEL) - mean*mean;
    float rinv = rsqrtf(var + 1e-5f);
    float4 gv = ((const float4*)g)[t];
    float4 sv = ((const float4*)s)[t];
    __half2* orow = (__half2*)(out + (size_t)row*DMODEL);
    orow[2*t  ] = __floats2half2_rn((v.x-mean)*rinv*gv.x + sv.x,
                                    (v.y-mean)*rinv*gv.y + sv.y);
    orow[2*t+1] = __floats2half2_rn((v.z-mean)*rinv*gv.z + sv.z,
                                    (v.w-mean)*rinv*gv.w + sv.w);
}

// ---------------- FP16 tensor-core GEMM (ldmatrix fragments) -----------------
// 128x128 CTA tile, 256 thr, 8 warps (2x4), warp tile 64x32 as 4x4 m16n8k16.
// K-slab 64 halfs, 2-stage cp.async double buffer, bounds(256,2).
// Fragments via ldmatrix: A x4 (4 instr/k-step), B x2 (4 instr/k-step).
// Row stride 72 halfs (144B): 8x8 row addrs hit banks 4r..4r+3 -> conflict-free.
// EPI: 1 +bias+residual(f32 C), 2 +bias+gelu(f16 C), 3 qkv scatter(f16).
struct GSmemH {
    __half As[2][128][72];
    __half Bs[2][128][72];
};
extern __shared__ char gsm_raw[];

template<int EPI>
__global__ __launch_bounds__(256,2) void hgemm_kernel(
    const __half* __restrict__ A, const __half* __restrict__ Bt,
    const float* __restrict__ bias, const float* __restrict__ res,
    void* __restrict__ Cv,
    __half* __restrict__ Oq, __half* __restrict__ Ok, __half* __restrict__ Ov,
    int M, int N, int K)
{
    GSmemH* sm = (GSmemH*)gsm_raw;
    int t = threadIdx.x;
    int lane = t & 31, w = t >> 5;
    int wm = w >> 2, wn = w & 3;        // warp grid 2 x 4
    int g = lane >> 2, tig = lane & 3;  // mma groupID / thread-in-group
    int m0 = blockIdx.y * 128, n0 = blockIdx.x * 128;

    const int crow = t >> 1, coff = (t & 1) * 32;   // halfs
    const __half* Ab = A  + (size_t)(m0 + crow)*K + coff;
    const __half* Bb = Bt + (size_t)(n0 + crow)*K + coff;

    // ldmatrix per-lane row/col offsets
    const int aR = (lane & 7) + 8*((lane >> 3) & 1);  // row 0..15
    const int aC = 8*(lane >> 4);                     // 0 or 8 (k)
    const int bR = lane & 7;
    const int bC = 8*((lane >> 3) & 1);
    uint32_t aB0 = smaddr(&sm->As[0][0][0]) + (uint32_t)(((wm*64 + aR)*72 + aC)*2);
    uint32_t aB1 = smaddr(&sm->As[1][0][0]) + (uint32_t)(((wm*64 + aR)*72 + aC)*2);
    uint32_t bB0 = smaddr(&sm->Bs[0][0][0]) + (uint32_t)(((wn*32 + bR)*72 + bC)*2);
    uint32_t bB1 = smaddr(&sm->Bs[1][0][0]) + (uint32_t)(((wn*32 + bR)*72 + bC)*2);

    float acc[4][4][4];
    #pragma unroll
    for (int i=0;i<4;i++)
    #pragma unroll
    for (int j=0;j<4;j++)
    #pragma unroll
    for (int r=0;r<4;r++) acc[i][j][r] = 0.0f;

    auto issue = [&](int buf, int slab){
        const __half* Ap = Ab + slab*64;
        const __half* Bp = Bb + slab*64;
        #pragma unroll
        for (int i=0;i<4;i++)
            cpa16(&sm->As[buf][crow][coff + 8*i], Ap + 8*i);
        #pragma unroll
        for (int i=0;i<4;i++)
            cpa16(&sm->Bs[buf][crow][coff + 8*i], Bp + 8*i);
    };

    issue(0, 0);
    CP_COMMIT();

    int nslab = K >> 6;
    for (int s=0; s<nslab; s++){
        int buf = s & 1;
        CP_WAIT0();
        __syncthreads();
        if (s + 1 < nslab){
            issue(buf ^ 1, s + 1);
            CP_COMMIT();
        }
        uint32_t ab = buf ? aB1 : aB0;
        uint32_t bb = buf ? bB1 : bB0;
        #pragma unroll
        for (int ks=0; ks<4; ks++){
            uint32_t kk2 = ks*32;               // 16 halfs = 32 bytes
            unsigned af[4][4], bf[4][2];
            #pragma unroll
            for (int mt=0; mt<4; mt++)
                ldsm_x4(af[mt], ab + mt*16*144 + kk2);
            #pragma unroll
            for (int nt=0; nt<4; nt++)
                ldsm_x2(bf[nt], bb + nt*8*144 + kk2);
            #pragma unroll
            for (int mt=0; mt<4; mt++)
            #pragma unroll
            for (int nt=0; nt<4; nt++)
                mma16(acc[mt][nt], af[mt], bf[nt]);
        }
    }

    // ---------------- epilogue ---------------
    #pragma unroll
    for (int mt=0; mt<4; mt++){
        #pragma unroll
        for (int nt=0; nt<4; nt++){
            int col = n0 + wn*32 + nt*8 + 2*tig;
            #pragma unroll
            for (int hh=0; hh<2; hh++){
                int row = m0 + wm*64 + mt*16 + g + hh*8;
                float vx = acc[mt][nt][hh*2+0], vy = acc[mt][nt][hh*2+1];
                if (EPI == 1){
                    float2 bb = *(const float2*)(bias + col);
                    float2 rr = *(const float2*)(res + (size_t)row*N + col);
                    *(float2*)((float*)Cv + (size_t)row*N + col) =
                        make_float2(vx + bb.x + rr.x, vy + bb.y + rr.y);
                } else if (EPI == 2){
                    float2 bb = *(const float2*)(bias + col);
                    *(__half2*)((__half*)Cv + (size_t)row*N + col) =
                        __floats2half2_rn(gelu_fast(vx + bb.x), gelu_fast(vy + bb.y));
                } else {
                    int which = col >> 10;
                    int h = (col >> 6) & (NH-1);
                    int d = col & (HD-1);
                    int b = row >> 11;
                    int sg = row & (SEQ-1);
                    __half* o = (which==0) ? Oq : ((which==1) ? Ok : Ov);
                    *(__half2*)(o + ((size_t)((b*NH + h)*SEQ + sg))*HD + d) =
                        __floats2half2_rn(vx, vy);
                }
            }
        }
    }
}

// ---------------- Flash attention (FP16 mma + ldmatrix, causal) --------------
// 64-query tile, 64-key steps, 128 threads / 4 warps; warp w owns query rows
// [w*16, w*16+16). V kept in natural [key][d] layout; PV uses ldmatrix.trans
// (no smem transpose stores). Row stride 72 halfs: conflict-free ldmatrix.
struct FlashSmemH {
    __half Qs[64][72];
    __half Ks[64][72];
    __half Vs[64][72];   // [key][d]
    __half Ps[64][72];
};
extern __shared__ char flash_dyn[];

__global__ __launch_bounds__(128) void flash_h_kernel(
    const __half* __restrict__ Q, const __half* __restrict__ K,
    const __half* __restrict__ V, __half* __restrict__ ctx)
{
    FlashSmemH* sm = (FlashSmemH*)flash_dyn;
    int t = threadIdx.x;
    int lane = t & 31, w = t >> 5;
    int g = lane >> 2, tig = lane & 3;
    int qb = blockIdx.x, bh = blockIdx.y;
    int mw = w * 16;

    const __half* Qb = Q + ((size_t)bh*SEQ + (size_t)qb*64)*HD;
    const __half* Kb = K + (size_t)bh*SEQ*HD;
    const __half* Vb = V + (size_t)bh*SEQ*HD;

    // ldmatrix per-lane offsets
    const int aR = (lane & 7) + 8*((lane >> 3) & 1);
    const int aC = 8*(lane >> 4);
    const int bR = lane & 7;
    const int bC = 8*((lane >> 3) & 1);
    uint32_t qBase = smaddr(&sm->Qs[0][0]) + (uint32_t)(((mw + aR)*72 + aC)*2);
    uint32_t kBase = smaddr(&sm->Ks[0][0]) + (uint32_t)((bR*72 + bC)*2);
    uint32_t pBase = smaddr(&sm->Ps[0][0]) + (uint32_t)(((mw + aR)*72 + aC)*2);
    // V trans: rows are keys; lanes 0-7 -> keys kk+0..7, lanes 8-15 -> kk+8..15
    uint32_t vBase = smaddr(&sm->Vs[0][0]) + (uint32_t)((((lane & 7) + 8*((lane >> 3) & 1))*72)*2);

    // load Q tile, softmax scale folded (0.125 exact in fp16)
    {
        __half2 sc = __floats2half2_rn(0.125f, 0.125f);
        #pragma unroll
        for (int u=0; u<4; u++){
            int cidx = t + 128*u;           // 512 items of 8 halfs
            int r = cidx >> 3, c = (cidx & 7) * 8;
            uint4 v = *(const uint4*)(Qb + r*HD + c);
            __half2* pv = (__half2*)&v;
            pv[0]=__hmul2(pv[0],sc); pv[1]=__hmul2(pv[1],sc);
            pv[2]=__hmul2(pv[2],sc); pv[3]=__hmul2(pv[3],sc);
            *(uint4*)&sm->Qs[r][c] = v;
        }
    }

    float m0 = -1e30f, m1 = -1e30f, l0 = 0.0f, l1 = 0.0f;
    float acc_o[8][4];
    #pragma unroll
    for (int nt=0; nt<8; nt++)
    #pragma unroll
    for (int r=0; r<4; r++) acc_o[nt][r] = 0.0f;

    for (int jt=0; jt<=qb; jt++){
        __syncthreads();            // previous tile's reads of Ks/Vs done
        const __half* Kp = Kb + (size_t)jt*64*HD;
        const __half* Vp = Vb + (size_t)jt*64*HD;
        #pragma unroll
        for (int u=0; u<4; u++){
            int cidx = t + 128*u;
            int r = cidx >> 3, c = (cidx & 7) * 8;   // r = key, c = d chunk
            *(uint4*)&sm->Ks[r][c] = *(const uint4*)(Kp + r*HD + c);
            *(uint4*)&sm->Vs[r][c] = *(const uint4*)(Vp + r*HD + c);
        }
        __syncthreads();

        // ---- S = Q @ K^T ----
        float acc_s[8][4];
        #pragma unroll
        for (int nt=0; nt<8; nt++)
        #pragma unroll
        for (int r=0; r<4; r++) acc_s[nt][r] = 0.0f;
        #pragma unroll
        for (int ks=0; ks<4; ks++){
            uint32_t kk2 = ks*32;
            unsigned af[4];
            ldsm_x4(af, qBase + kk2);
            #pragma unroll
            for (int nt=0; nt<8; nt++){
                unsigned bf[2];
                ldsm_x2(bf, kBase + nt*8*144 + kk2);
                mma16(acc_s[nt], af, bf);
            }
        }

        // ---- causal mask on diagonal tile ----
        if (jt == qb){
            int i0 = mw + g;
            #pragma unroll
            for (int nt=0; nt<8; nt++){
                int j = nt*8 + 2*tig;
                if (j   > i0)   acc_s[nt][0] = -1e30f;
                if (j+1 > i0)   acc_s[nt][1] = -1e30f;
                if (j   > i0+8) acc_s[nt][2] = -1e30f;
                if (j+1 > i0+8) acc_s[nt][3] = -1e30f;
            }
        }

        // ---- online softmax (rows g, g+8; quad reduce) ----
        float mx0 = -1e30f, mx1 = -1e30f;
        #pragma unroll
        for (int nt=0; nt<8; nt++){
            mx0 = fmaxf(mx0, fmaxf(acc_s[nt][0], acc_s[nt][1]));
            mx1 = fmaxf(mx1, fmaxf(acc_s[nt][2], acc_s[nt][3]));
        }
        mx0 = fmaxf(mx0, __shfl_xor_sync(0xffffffffu, mx0, 1));
        mx0 = fmaxf(mx0, __shfl_xor_sync(0xffffffffu, mx0, 2));
        mx1 = fmaxf(mx1, __shfl_xor_sync(0xffffffffu, mx1, 1));
        mx1 = fmaxf(mx1, __shfl_xor_sync(0xffffffffu, mx1, 2));
        float mn0 = fmaxf(m0, mx0), mn1 = fmaxf(m1, mx1);
        float al0 = __expf(m0 - mn0), al1 = __expf(m1 - mn1);
        float s0 = 0.0f, s1 = 0.0f;
        #pragma unroll
        for (int nt=0; nt<8; nt++){
            float p00 = __expf(acc_s[nt][0] - mn0);
            float p01 = __expf(acc_s[nt][1] - mn0);
            float p10 = __expf(acc_s[nt][2] - mn1);
            float p11 = __expf(acc_s[nt][3] - mn1);
            s0 += p00 + p01; s1 += p10 + p11;
            *(__half2*)&sm->Ps[mw+g  ][nt*8 + 2*tig] = __floats2half2_rn(p00, p01);
            *(__half2*)&sm->Ps[mw+g+8][nt*8 + 2*tig] = __floats2half2_rn(p10, p11);
        }
        s0 += __shfl_xor_sync(0xffffffffu, s0, 1);
        s0 += __shfl_xor_sync(0xffffffffu, s0, 2);
        s1 += __shfl_xor_sync(0xffffffffu, s1, 1);
        s1 += __shfl_xor_sync(0xffffffffu, s1, 2);
        m0 = mn0; m1 = mn1;
        l0 = l0*al0 + s0; l1 = l1*al1 + s1;
        #pragma unroll
        for (int nt=0; nt<8; nt++){
            acc_o[nt][0] *= al0; acc_o[nt][1] *= al0;
            acc_o[nt][2] *= al1; acc_o[nt][3] *= al1;
        }

        __syncwarp();               // P visibility within owning warp

        // ---- O += P @ V  (B via ldmatrix.trans on natural V layout) ----
        #pragma unroll
        for (int ks=0; ks<4; ks++){
            unsigned af[4];
            ldsm_x4(af, pBase + ks*32);
            #pragma unroll
            for (int nt=0; nt<8; nt++){
                unsigned bf[2];
                ldsm_x2t(bf, vBase + ks*16*144 + nt*16);
                mma16(acc_o[nt], af, bf);
            }
        }
    }

    // normalize, write fp16 ctx in [B,S,D] (feeds Wout GEMM A operand)
    float inv0 = 1.0f/l0, inv1 = 1.0f/l1;
    int b = bh >> 4, h = bh & (NH-1);
    int r0 = qb*64 + mw + g, r1 = r0 + 8;
    #pragma unroll
    for (int nt=0; nt<8; nt++){
        int col = h*HD + nt*8 + 2*tig;
        *(__half2*)(ctx + (size_t)(b*SEQ + r0)*DMODEL + col) =
            __floats2half2_rn(acc_o[nt][0]*inv0, acc_o[nt][1]*inv0);
        *(__half2*)(ctx + (size_t)(b*SEQ + r1)*DMODEL + col) =
            __floats2half2_rn(acc_o[nt][2]*inv1, acc_o[nt][3]*inv1);
    }
}

// ---------------- launch ----------------------------------------------------
extern "C" void kernel_launch(void* const* d_in, const int* in_sizes, int n_in,
                              void* d_out, int out_size)
{
    (void)in_sizes; (void)n_in; (void)out_size;
    const float* x    = (const float*)d_in[0];
    const float* Wqkv = (const float*)d_in[1];
    const float* Wout = (const float*)d_in[2];
    const float* bout = (const float*)d_in[3];
    const float* W1   = (const float*)d_in[4];
    const float* b1   = (const float*)d_in[5];
    const float* W2   = (const float*)d_in[6];
    const float* b2   = (const float*)d_in[7];
    const float* g1   = (const float*)d_in[8];
    const float* s1   = (const float*)d_in[9];
    const float* g2   = (const float*)d_in[10];
    const float* s2   = (const float*)d_in[11];
    float* out = (float*)d_out;

    __half *p_ln, *p_q, *p_k, *p_v, *p_ctx, *p_h2;
    __half *p_wqkvT, *p_woutT, *p_w1T, *p_w2T;
    float *p_x1;
    cudaGetSymbolAddress((void**)&p_ln,  g_ln);
    cudaGetSymbolAddress((void**)&p_q,   g_q);
    cudaGetSymbolAddress((void**)&p_k,   g_k);
    cudaGetSymbolAddress((void**)&p_v,   g_v);
    cudaGetSymbolAddress((void**)&p_ctx, g_ctx);
    cudaGetSymbolAddress((void**)&p_x1,  g_x1);
    cudaGetSymbolAddress((void**)&p_h2,  g_h2);
    cudaGetSymbolAddress((void**)&p_wqkvT, g_wqkvT);
    cudaGetSymbolAddress((void**)&p_woutT, g_woutT);
    cudaGetSymbolAddress((void**)&p_w1T,   g_w1T);
    cudaGetSymbolAddress((void**)&p_w2T,   g_w2T);

    const int gsmem = (int)sizeof(GSmemH);
    const int fsmem = (int)sizeof(FlashSmemH);
    cudaFuncSetAttribute(hgemm_kernel<1>, cudaFuncAttributeMaxDynamicSharedMemorySize, gsmem);
    cudaFuncSetAttribute(hgemm_kernel<2>, cudaFuncAttributeMaxDynamicSharedMemorySize, gsmem);
    cudaFuncSetAttribute(hgemm_kernel<3>, cudaFuncAttributeMaxDynamicSharedMemorySize, gsmem);
    cudaFuncSetAttribute(flash_h_kernel, cudaFuncAttributeMaxDynamicSharedMemorySize, fsmem);

    // 0) weight transpose + fp16 convert (once per launch; ~30us total)
    transh_kernel<<<dim3(3*DMODEL/32, DMODEL/32), 256>>>(Wqkv, p_wqkvT, DMODEL, 3*DMODEL);
    transh_kernel<<<dim3(DMODEL/32,   DMODEL/32), 256>>>(Wout, p_woutT, DMODEL, DMODEL);
    transh_kernel<<<dim3(DFF/32,      DMODEL/32), 256>>>(W1,   p_w1T,   DMODEL, DFF);
    transh_kernel<<<dim3(DMODEL/32,   DFF/32),    256>>>(W2,   p_w2T,   DFF,    DMODEL);

    // 1) ln1 -> fp16
    ln_kernel<<<NTOK, 256>>>(x, g1, s1, p_ln);
    // 2) qkv gemm (fp16 mma) + scatter to fp16 [B,H,S,HD]
    hgemm_kernel<3><<<dim3(3*DMODEL/128, NTOK/128), 256, gsmem>>>(
        p_ln, p_wqkvT, nullptr, nullptr, nullptr, p_q, p_k, p_v,
        NTOK, 3*DMODEL, DMODEL);
    // 3) causal flash attention (fp16 mma + ldmatrix)
    flash_h_kernel<<<dim3(SEQ/64, NB*NH), 128, fsmem>>>(p_q, p_k, p_v, p_ctx);
    // 4) out proj + bias + residual(x) -> f32 x1
    hgemm_kernel<1><<<dim3(DMODEL/128, NTOK/128), 256, gsmem>>>(
        p_ctx, p_woutT, bout, x, p_x1, nullptr, nullptr, nullptr,
        NTOK, DMODEL, DMODEL);
    // 5) ln2 -> fp16
    ln_kernel<<<NTOK, 256>>>(p_x1, g2, s2, p_ln);
    // 6) W1 + bias + gelu -> fp16 h2
    hgemm_kernel<2><<<dim3(DFF/128, NTOK/128), 256, gsmem>>>(
        p_ln, p_w1T, b1, nullptr, p_h2, nullptr, nullptr, nullptr,
        NTOK, DFF, DMODEL);
    // 7) W2 + bias + residual(x1) -> f32 out
    hgemm_kernel<1><<<dim3(DMODEL/128, NTOK/128), 256, gsmem>>>(
        p_h2, p_w2T, b2, p_x1, out, nullptr, nullptr, nullptr,
        NTOK, DMODEL, DFF);
}

// round 17
// speedup vs baseline: 2.7874x; 1.0170x over previous
#include <cuda_runtime.h>
#include <cuda_fp16.h>
#include <math.h>
#include <stdint.h>

#define NB 4
#define SEQ 2048
#define DMODEL 1024
#define NH 16
#define HD 64
#define NTOK (NB*SEQ)      /* 8192 */
#define DFF 4096

// ---------------- scratch (device globals; no allocations allowed) ----------
__device__ __half g_ln [(size_t)NTOK*DMODEL];
__device__ __half g_q  [(size_t)NTOK*DMODEL];
__device__ __half g_k  [(size_t)NTOK*DMODEL];
__device__ __half g_v  [(size_t)NTOK*DMODEL];
__device__ __half g_ctx[(size_t)NTOK*DMODEL];
__device__ float  g_x1 [(size_t)NTOK*DMODEL];
__device__ __half g_h2 [(size_t)NTOK*DFF];
// fp16 transposed weights: Wt[n][k] = fp16(W[k][n])
__device__ __half g_wqkvT[(size_t)3*DMODEL*DMODEL];
__device__ __half g_woutT[(size_t)DMODEL*DMODEL];
__device__ __half g_w1T  [(size_t)DFF*DMODEL];
__device__ __half g_w2T  [(size_t)DMODEL*DFF];

// ---------------- helpers ----------------------------------------------------
__device__ __forceinline__ float gelu_fast(float x){
    float u = 0.7978845608028654f*(x + 0.044715f*x*x*x);
    float th; asm("tanh.approx.f32 %0, %1;" : "=f"(th) : "f"(u));
    return 0.5f*x*(1.0f + th);
}
__device__ __forceinline__ void mma16(float* c, const unsigned* a, const unsigned* b){
    asm volatile(
        "mma.sync.aligned.m16n8k16.row.col.f32.f16.f16.f32 "
        "{%0,%1,%2,%3}, {%4,%5,%6,%7}, {%8,%9}, {%0,%1,%2,%3};\n"
        : "+f"(c[0]), "+f"(c[1]), "+f"(c[2]), "+f"(c[3])
        : "r"(a[0]), "r"(a[1]), "r"(a[2]), "r"(a[3]), "r"(b[0]), "r"(b[1]));
}
__device__ __forceinline__ void ldsm_x4(unsigned* r, uint32_t addr){
    asm volatile("ldmatrix.sync.aligned.m8n8.x4.shared.b16 {%0,%1,%2,%3}, [%4];"
        : "=r"(r[0]), "=r"(r[1]), "=r"(r[2]), "=r"(r[3]) : "r"(addr));
}
__device__ __forceinline__ void ldsm_x4t(unsigned* r, uint32_t addr){
    asm volatile("ldmatrix.sync.aligned.m8n8.x4.trans.shared.b16 {%0,%1,%2,%3}, [%4];"
        : "=r"(r[0]), "=r"(r[1]), "=r"(r[2]), "=r"(r[3]) : "r"(addr));
}
__device__ __forceinline__ uint32_t smaddr(const void* p){
    return (uint32_t)__cvta_generic_to_shared(p);
}
__device__ __forceinline__ void cpa16(void* smem_dst, const void* gsrc){
    unsigned d = (unsigned)__cvta_generic_to_shared(smem_dst);
    asm volatile("cp.async.cg.shared.global [%0], [%1], 16;\n" :: "r"(d), "l"(gsrc));
}
#define CP_COMMIT() asm volatile("cp.async.commit_group;\n" ::: "memory")
#define CP_WAIT0()  asm volatile("cp.async.wait_group 0;\n" ::: "memory")

// ---------------- weight transpose + fp16 convert -----------------------------
__global__ __launch_bounds__(256) void transh_kernel(
    const float* __restrict__ src, __half* __restrict__ dst, int K, int N)
{
    __shared__ float tile[32][33];
    int k0 = blockIdx.y*32, n0 = blockIdx.x*32;
    int tx = threadIdx.x & 31, ty = threadIdx.x >> 5;  // 32 x 8
    #pragma unroll
    for (int i=0;i<32;i+=8)
        tile[ty+i][tx] = src[(size_t)(k0+ty+i)*N + n0+tx];
    __syncthreads();
    #pragma unroll
    for (int i=0;i<32;i+=8)
        dst[(size_t)(n0+ty+i)*K + k0+tx] = __float2half_rn(tile[tx][ty+i]);
}

// ---------------- LayerNorm (fp16 output) ------------------------------------
__global__ __launch_bounds__(256) void ln_kernel(const float* __restrict__ x,
        const float* __restrict__ g, const float* __restrict__ s,
        __half* __restrict__ out)
{
    int row = blockIdx.x;
    int t = threadIdx.x;
    const float4* xr = (const float4*)(x + (size_t)row*DMODEL);
    float4 v = xr[t];
    float sum = v.x+v.y+v.z+v.w;
    float sq  = v.x*v.x+v.y*v.y+v.z*v.z+v.w*v.w;
    #pragma unroll
    for (int o=16;o>0;o>>=1){
        sum += __shfl_xor_sync(0xffffffffu, sum, o);
        sq  += __shfl_xor_sync(0xffffffffu, sq , o);
    }
    __shared__ float red[16];
    if ((t&31)==0){ red[t>>5] = sum; red[8+(t>>5)] = sq; }
    __syncthreads();
    sum = 0.0f; sq = 0.0f;
    #pragma unroll
    for (int w=0; w<8; w++){ sum += red[w]; sq += red[8+w]; }
    float mean = sum * (1.0f/DMODEL);
    float var  = sq  * (1.0f/DMODEL) - mean*mean;
    float rinv = rsqrtf(var + 1e-5f);
    float4 gv = ((const float4*)g)[t];
    float4 sv = ((const float4*)s)[t];
    __half2* orow = (__half2*)(out + (size_t)row*DMODEL);
    orow[2*t  ] = __floats2half2_rn((v.x-mean)*rinv*gv.x + sv.x,
                                    (v.y-mean)*rinv*gv.y + sv.y);
    orow[2*t+1] = __floats2half2_rn((v.z-mean)*rinv*gv.z + sv.z,
                                    (v.w-mean)*rinv*gv.w + sv.w);
}

// ---------------- FP16 tensor-core GEMM (ldmatrix, paired B x4) --------------
// 128x128 CTA tile, 256 thr, 8 warps (2x4), warp tile 64x32 as 4x4 m16n8k16.
// K-slab 64 halfs, 2-stage cp.async double buffer, bounds(256,2).
// Per k-step: A 4x ldsm_x4, B 2x ldsm_x4 (each covers two n-tiles) -> 6 LDSM.
// EPI: 1 +bias+residual(f32 C), 2 +bias+gelu(f16 C), 3 qkv scatter(f16).
struct GSmemH {
    __half As[2][128][72];
    __half Bs[2][128][72];
};
extern __shared__ char gsm_raw[];

template<int EPI>
__global__ __launch_bounds__(256,2) void hgemm_kernel(
    const __half* __restrict__ A, const __half* __restrict__ Bt,
    const float* __restrict__ bias, const float* __restrict__ res,
    void* __restrict__ Cv,
    __half* __restrict__ Oq, __half* __restrict__ Ok, __half* __restrict__ Ov,
    int M, int N, int K)
{
    GSmemH* sm = (GSmemH*)gsm_raw;
    int t = threadIdx.x;
    int lane = t & 31, w = t >> 5;
    int wm = w >> 2, wn = w & 3;        // warp grid 2 x 4
    int g = lane >> 2, tig = lane & 3;  // mma groupID / thread-in-group
    int m0 = blockIdx.y * 128, n0 = blockIdx.x * 128;

    const int crow = t >> 1, coff = (t & 1) * 32;   // halfs
    const __half* Ab = A  + (size_t)(m0 + crow)*K + coff;
    const __half* Bb = Bt + (size_t)(n0 + crow)*K + coff;

    // ldmatrix per-lane addresses
    const int aR = (lane & 7) + 8*((lane >> 3) & 1);  // A: row 0..15 in 16-grp
    const int aC = 8*(lane >> 4);                     // A: k 0 or 8
    const int bR = (lane & 7) + 8*(lane >> 4);        // B x4-pair: row 0..15
    const int bC = 8*((lane >> 3) & 1);               // B: k 0 or 8
    uint32_t aB0 = smaddr(&sm->As[0][0][0]) + (uint32_t)(((wm*64 + aR)*72 + aC)*2);
    uint32_t aB1 = smaddr(&sm->As[1][0][0]) + (uint32_t)(((wm*64 + aR)*72 + aC)*2);
    uint32_t bB0 = smaddr(&sm->Bs[0][0][0]) + (uint32_t)(((wn*32 + bR)*72 + bC)*2);
    uint32_t bB1 = smaddr(&sm->Bs[1][0][0]) + (uint32_t)(((wn*32 + bR)*72 + bC)*2);

    float acc[4][4][4];
    #pragma unroll
    for (int i=0;i<4;i++)
    #pragma unroll
    for (int j=0;j<4;j++)
    #pragma unroll
    for (int r=0;r<4;r++) acc[i][j][r] = 0.0f;

    auto issue = [&](int buf, int slab){
        const __half* Ap = Ab + slab*64;
        const __half* Bp = Bb + slab*64;
        #pragma unroll
        for (int i=0;i<4;i++)
            cpa16(&sm->As[buf][crow][coff + 8*i], Ap + 8*i);
        #pragma unroll
        for (int i=0;i<4;i++)
            cpa16(&sm->Bs[buf][crow][coff + 8*i], Bp + 8*i);
    };

    issue(0, 0);
    CP_COMMIT();

    int nslab = K >> 6;
    for (int s=0; s<nslab; s++){
        int buf = s & 1;
        CP_WAIT0();
        __syncthreads();
        if (s + 1 < nslab){
            issue(buf ^ 1, s + 1);
            CP_COMMIT();
        }
        uint32_t ab = buf ? aB1 : aB0;
        uint32_t bb = buf ? bB1 : bB0;
        #pragma unroll
        for (int ks=0; ks<4; ks++){
            uint32_t kk2 = ks*32;               // 16 halfs = 32 bytes
            unsigned af[4][4], bf[4][2];
            #pragma unroll
            for (int mt=0; mt<4; mt++)
                ldsm_x4(af[mt], ab + mt*16*144 + kk2);
            #pragma unroll
            for (int nt2=0; nt2<2; nt2++)
                ldsm_x4(&bf[2*nt2][0], bb + nt2*16*144 + kk2);
            #pragma unroll
            for (int mt=0; mt<4; mt++)
            #pragma unroll
            for (int nt=0; nt<4; nt++)
                mma16(acc[mt][nt], af[mt], bf[nt]);
        }
    }

    // ---------------- epilogue ---------------
    #pragma unroll
    for (int mt=0; mt<4; mt++){
        #pragma unroll
        for (int nt=0; nt<4; nt++){
            int col = n0 + wn*32 + nt*8 + 2*tig;
            #pragma unroll
            for (int hh=0; hh<2; hh++){
                int row = m0 + wm*64 + mt*16 + g + hh*8;
                float vx = acc[mt][nt][hh*2+0], vy = acc[mt][nt][hh*2+1];
                if (EPI == 1){
                    float2 bb = *(const float2*)(bias + col);
                    float2 rr = *(const float2*)(res + (size_t)row*N + col);
                    *(float2*)((float*)Cv + (size_t)row*N + col) =
                        make_float2(vx + bb.x + rr.x, vy + bb.y + rr.y);
                } else if (EPI == 2){
                    float2 bb = *(const float2*)(bias + col);
                    *(__half2*)((__half*)Cv + (size_t)row*N + col) =
                        __floats2half2_rn(gelu_fast(vx + bb.x), gelu_fast(vy + bb.y));
                } else {
                    int which = col >> 10;
                    int h = (col >> 6) & (NH-1);
                    int d = col & (HD-1);
                    int b = row >> 11;
                    int sg = row & (SEQ-1);
                    __half* o = (which==0) ? Oq : ((which==1) ? Ok : Ov);
                    *(__half2*)(o + ((size_t)((b*NH + h)*SEQ + sg))*HD + d) =
                        __floats2half2_rn(vx, vy);
                }
            }
        }
    }
}

// ---------------- Flash attention (FP16 mma + ldmatrix, causal) --------------
// 128-query tile, 64-key steps, 256 threads / 8 warps; warp w owns query rows
// [w*16, w*16+16). K/V tiles serve 128 queries (half the traffic of 64-q).
// K via paired ldsm_x4, V via paired ldsm_x4.trans (natural [key][d] layout).
// Row stride 72 halfs: conflict-free ldmatrix.
struct FlashSmemH {
    __half Qs[128][72];
    __half Ks[64][72];
    __half Vs[64][72];   // [key][d]
    __half Ps[128][72];
};
extern __shared__ char flash_dyn[];

__global__ __launch_bounds__(256) void flash_h_kernel(
    const __half* __restrict__ Q, const __half* __restrict__ K,
    const __half* __restrict__ V, __half* __restrict__ ctx)
{
    FlashSmemH* sm = (FlashSmemH*)flash_dyn;
    int t = threadIdx.x;
    int lane = t & 31, w = t >> 5;
    int g = lane >> 2, tig = lane & 3;
    int qb = blockIdx.x, bh = blockIdx.y;
    int mw = w * 16;

    const __half* Qb = Q + ((size_t)bh*SEQ + (size_t)qb*128)*HD;
    const __half* Kb = K + (size_t)bh*SEQ*HD;
    const __half* Vb = V + (size_t)bh*SEQ*HD;

    // ldmatrix per-lane offsets
    const int aR = (lane & 7) + 8*((lane >> 3) & 1);
    const int aC = 8*(lane >> 4);
    const int bR = (lane & 7) + 8*(lane >> 4);        // K pair rows 0..15
    const int bC = 8*((lane >> 3) & 1);
    uint32_t qBase = smaddr(&sm->Qs[0][0]) + (uint32_t)(((mw + aR)*72 + aC)*2);
    uint32_t kBase = smaddr(&sm->Ks[0][0]) + (uint32_t)((bR*72 + bC)*2);
    uint32_t pBase = smaddr(&sm->Ps[0][0]) + (uint32_t)(((mw + aR)*72 + aC)*2);
    // V x4.trans: rows = keys (lane&7)+8*((lane>>3)&1) in 16-key grp; col n via lane>>4
    uint32_t vBase = smaddr(&sm->Vs[0][0]) +
        (uint32_t)((((lane & 7) + 8*((lane >> 3) & 1))*72)*2 + 16*(lane >> 4));

    // load Q tile, softmax scale folded (0.125 exact in fp16)
    {
        __half2 sc = __floats2half2_rn(0.125f, 0.125f);
        #pragma unroll
        for (int u=0; u<4; u++){
            int cidx = t + 256*u;           // 1024 items of 8 halfs
            int r = cidx >> 3, c = (cidx & 7) * 8;
            uint4 v = *(const uint4*)(Qb + r*HD + c);
            __half2* pv = (__half2*)&v;
            pv[0]=__hmul2(pv[0],sc); pv[1]=__hmul2(pv[1],sc);
            pv[2]=__hmul2(pv[2],sc); pv[3]=__hmul2(pv[3],sc);
            *(uint4*)&sm->Qs[r][c] = v;
        }
    }

    float m0 = -1e30f, m1 = -1e30f, l0 = 0.0f, l1 = 0.0f;
    float acc_o[8][4];
    #pragma unroll
    for (int nt=0; nt<8; nt++)
    #pragma unroll
    for (int r=0; r<4; r++) acc_o[nt][r] = 0.0f;

    int nkv = 2*qb + 2;                 // kv tiles 0 .. 2qb+1
    for (int jt=0; jt<nkv; jt++){
        __syncthreads();                // previous tile's reads of Ks/Vs done
        const __half* Kp = Kb + (size_t)jt*64*HD;
        const __half* Vp = Vb + (size_t)jt*64*HD;
        #pragma unroll
        for (int u=0; u<2; u++){
            int cidx = t + 256*u;
            int r = cidx >> 3, c = (cidx & 7) * 8;   // r = key, c = d chunk
            *(uint4*)&sm->Ks[r][c] = *(const uint4*)(Kp + r*HD + c);
            *(uint4*)&sm->Vs[r][c] = *(const uint4*)(Vp + r*HD + c);
        }
        __syncthreads();

        // ---- S = Q @ K^T ----
        float acc_s[8][4];
        #pragma unroll
        for (int nt=0; nt<8; nt++)
        #pragma unroll
        for (int r=0; r<4; r++) acc_s[nt][r] = 0.0f;
        #pragma unroll
        for (int ks=0; ks<4; ks++){
            uint32_t kk2 = ks*32;
            unsigned af[4];
            ldsm_x4(af, qBase + kk2);
            #pragma unroll
            for (int nt2=0; nt2<4; nt2++){
                unsigned bf[2][2];
                ldsm_x4(&bf[0][0], kBase + nt2*16*144 + kk2);
                mma16(acc_s[2*nt2  ], af, bf[0]);
                mma16(acc_s[2*nt2+1], af, bf[1]);
            }
        }

        // ---- causal mask (active only on the last two kv tiles) ----
        if (jt >= 2*qb){
            int joff = jt*64 - qb*128;  // 0 or 64
            int i0 = mw + g;
            #pragma unroll
            for (int nt=0; nt<8; nt++){
                int j = joff + nt*8 + 2*tig;
                if (j   > i0)   acc_s[nt][0] = -1e30f;
                if (j+1 > i0)   acc_s[nt][1] = -1e30f;
                if (j   > i0+8) acc_s[nt][2] = -1e30f;
                if (j+1 > i0+8) acc_s[nt][3] = -1e30f;
            }
        }

        // ---- online softmax (rows g, g+8; quad reduce) ----
        float mx0 = -1e30f, mx1 = -1e30f;
        #pragma unroll
        for (int nt=0; nt<8; nt++){
            mx0 = fmaxf(mx0, fmaxf(acc_s[nt][0], acc_s[nt][1]));
            mx1 = fmaxf(mx1, fmaxf(acc_s[nt][2], acc_s[nt][3]));
        }
        mx0 = fmaxf(mx0, __shfl_xor_sync(0xffffffffu, mx0, 1));
        mx0 = fmaxf(mx0, __shfl_xor_sync(0xffffffffu, mx0, 2));
        mx1 = fmaxf(mx1, __shfl_xor_sync(0xffffffffu, mx1, 1));
        mx1 = fmaxf(mx1, __shfl_xor_sync(0xffffffffu, mx1, 2));
        float mn0 = fmaxf(m0, mx0), mn1 = fmaxf(m1, mx1);
        float al0 = __expf(m0 - mn0), al1 = __expf(m1 - mn1);
        float s0 = 0.0f, s1 = 0.0f;
        #pragma unroll
        for (int nt=0; nt<8; nt++){
            float p00 = __expf(acc_s[nt][0] - mn0);
            float p01 = __expf(acc_s[nt][1] - mn0);
            float p10 = __expf(acc_s[nt][2] - mn1);
            float p11 = __expf(acc_s[nt][3] - mn1);
            s0 += p00 + p01; s1 += p10 + p11;
            *(__half2*)&sm->Ps[mw+g  ][nt*8 + 2*tig] = __floats2half2_rn(p00, p01);
            *(__half2*)&sm->Ps[mw+g+8][nt*8 + 2*tig] = __floats2half2_rn(p10, p11);
        }
        s0 += __shfl_xor_sync(0xffffffffu, s0, 1);
        s0 += __shfl_xor_sync(0xffffffffu, s0, 2);
        s1 += __shfl_xor_sync(0xffffffffu, s1, 1);
        s1 += __shfl_xor_sync(0xffffffffu, s1, 2);
        m0 = mn0; m1 = mn1;
        l0 = l0*al0 + s0; l1 = l1*al1 + s1;
        #pragma unroll
        for (int nt=0; nt<8; nt++){
            acc_o[nt][0] *= al0; acc_o[nt][1] *= al0;
            acc_o[nt][2] *= al1; acc_o[nt][3] *= al1;
        }

        __syncwarp();               // P visibility within owning warp

        // ---- O += P @ V  (B via paired ldmatrix.x4.trans on natural V) ----
        #pragma unroll
        for (int ks=0; ks<4; ks++){
            unsigned af[4];
            ldsm_x4(af, pBase + ks*32);
            #pragma unroll
            for (int nt2=0; nt2<4; nt2++){
                unsigned bf[2][2];
                ldsm_x4t(&bf[0][0], vBase + ks*16*144 + nt2*32);
                mma16(acc_o[2*nt2  ], af, bf[0]);
                mma16(acc_o[2*nt2+1], af, bf[1]);
            }
        }
    }

    // normalize, write fp16 ctx in [B,S,D] (feeds Wout GEMM A operand)
    float inv0 = 1.0f/l0, inv1 = 1.0f/l1;
    int b = bh >> 4, h = bh & (NH-1);
    int r0 = qb*128 + mw + g, r1 = r0 + 8;
    #pragma unroll
    for (int nt=0; nt<8; nt++){
        int col = h*HD + nt*8 + 2*tig;
        *(__half2*)(ctx + (size_t)(b*SEQ + r0)*DMODEL + col) =
            __floats2half2_rn(acc_o[nt][0]*inv0, acc_o[nt][1]*inv0);
        *(__half2*)(ctx + (size_t)(b*SEQ + r1)*DMODEL + col) =
            __floats2half2_rn(acc_o[nt][2]*inv1, acc_o[nt][3]*inv1);
    }
}

// ---------------- launch ----------------------------------------------------
extern "C" void kernel_launch(void* const* d_in, const int* in_sizes, int n_in,
                              void* d_out, int out_size)
{
    (void)in_sizes; (void)n_in; (void)out_size;
    const float* x    = (const float*)d_in[0];
    const float* Wqkv = (const float*)d_in[1];
    const float* Wout = (const float*)d_in[2];
    const float* bout = (const float*)d_in[3];
    const float* W1   = (const float*)d_in[4];
    const float* b1   = (const float*)d_in[5];
    const float* W2   = (const float*)d_in[6];
    const float* b2   = (const float*)d_in[7];
    const float* g1   = (const float*)d_in[8];
    const float* s1   = (const float*)d_in[9];
    const float* g2   = (const float*)d_in[10];
    const float* s2   = (const float*)d_in[11];
    float* out = (float*)d_out;

    __half *p_ln, *p_q, *p_k, *p_v, *p_ctx, *p_h2;
    __half *p_wqkvT, *p_woutT, *p_w1T, *p_w2T;
    float *p_x1;
    cudaGetSymbolAddress((void**)&p_ln,  g_ln);
    cudaGetSymbolAddress((void**)&p_q,   g_q);
    cudaGetSymbolAddress((void**)&p_k,   g_k);
    cudaGetSymbolAddress((void**)&p_v,   g_v);
    cudaGetSymbolAddress((void**)&p_ctx, g_ctx);
    cudaGetSymbolAddress((void**)&p_x1,  g_x1);
    cudaGetSymbolAddress((void**)&p_h2,  g_h2);
    cudaGetSymbolAddress((void**)&p_wqkvT, g_wqkvT);
    cudaGetSymbolAddress((void**)&p_woutT, g_woutT);
    cudaGetSymbolAddress((void**)&p_w1T,   g_w1T);
    cudaGetSymbolAddress((void**)&p_w2T,   g_w2T);

    const int gsmem = (int)sizeof(GSmemH);
    const int fsmem = (int)sizeof(FlashSmemH);
    cudaFuncSetAttribute(hgemm_kernel<1>, cudaFuncAttributeMaxDynamicSharedMemorySize, gsmem);
    cudaFuncSetAttribute(hgemm_kernel<2>, cudaFuncAttributeMaxDynamicSharedMemorySize, gsmem);
    cudaFuncSetAttribute(hgemm_kernel<3>, cudaFuncAttributeMaxDynamicSharedMemorySize, gsmem);
    cudaFuncSetAttribute(flash_h_kernel, cudaFuncAttributeMaxDynamicSharedMemorySize, fsmem);

    // 0) weight transpose + fp16 convert (once per launch; ~30us total)
    transh_kernel<<<dim3(3*DMODEL/32, DMODEL/32), 256>>>(Wqkv, p_wqkvT, DMODEL, 3*DMODEL);
    transh_kernel<<<dim3(DMODEL/32,   DMODEL/32), 256>>>(Wout, p_woutT, DMODEL, DMODEL);
    transh_kernel<<<dim3(DFF/32,      DMODEL/32), 256>>>(W1,   p_w1T,   DMODEL, DFF);
    transh_kernel<<<dim3(DMODEL/32,   DFF/32),    256>>>(W2,   p_w2T,   DFF,    DMODEL);

    // 1) ln1 -> fp16
    ln_kernel<<<NTOK, 256>>>(x, g1, s1, p_ln);
    // 2) qkv gemm (fp16 mma) + scatter to fp16 [B,H,S,HD]
    hgemm_kernel<3><<<dim3(3*DMODEL/128, NTOK/128), 256, gsmem>>>(
        p_ln, p_wqkvT, nullptr, nullptr, nullptr, p_q, p_k, p_v,
        NTOK, 3*DMODEL, DMODEL);
    // 3) causal flash attention (fp16 mma + ldmatrix; 128-query tiles)
    flash_h_kernel<<<dim3(SEQ/128, NB*NH), 256, fsmem>>>(p_q, p_k, p_v, p_ctx);
    // 4) out proj + bias + residual(x) -> f32 x1
    hgemm_kernel<1><<<dim3(DMODEL/128, NTOK/128), 256, gsmem>>>(
        p_ctx, p_woutT, bout, x, p_x1, nullptr, nullptr, nullptr,
        NTOK, DMODEL, DMODEL);
    // 5) ln2 -> fp16
    ln_kernel<<<NTOK, 256>>>(p_x1, g2, s2, p_ln);
    // 6) W1 + bias + gelu -> fp16 h2
    hgemm_kernel<2><<<dim3(DFF/128, NTOK/128), 256, gsmem>>>(
        p_ln, p_w1T, b1, nullptr, p_h2, nullptr, nullptr, nullptr,
        NTOK, DFF, DMODEL);
    // 7) W2 + bias + residual(x1) -> f32 out
    hgemm_kernel<1><<<dim3(DMODEL/128, NTOK/128), 256, gsmem>>>(
        p_h2, p_w2T, b2, p_x1, out, nullptr, nullptr, nullptr,
        NTOK, DMODEL, DFF);
}